// round 11
// baseline (speedup 1.0000x reference)
#include <cuda_runtime.h>
#include <math.h>
#include <stdint.h>

#define DIM 2048
#define NH 16
#define NKV 4
#define HD 128
#define BB 4
#define SS 2048
#define KVD 512        // NKV*HD
#define QKVD 3072      // DIM + 2*KVD
#define MROWS (BB*SS)  // 8192
#define ATTN_SCALE 0.08838834764831845f  // 1/sqrt(128)

// ---------------- scratch (no allocations allowed) ----------------
__device__ float    g_qkv[(size_t)BB*SS*QKVD];     // fp32 gemm outputs
__device__ float    g_q[(size_t)BB*NH*SS*HD];      // tf32 bits (scale folded)
__device__ float    g_k[(size_t)BB*NKV*SS*HD];     // tf32 bits
__device__ float    g_v[(size_t)BB*NKV*SS*HD];     // tf32 bits
__device__ uint32_t g_y[(size_t)BB*SS*DIM];        // tf32 bits (attn out)
__device__ uint32_t g_xt[(size_t)MROWS*DIM];       // tf32 bits of x
__device__ uint32_t g_wt[(size_t)QKVD*DIM];        // tf32 bits Wq|Wk|Wv
__device__ uint32_t g_wpt[(size_t)DIM*DIM];        // tf32 bits Wproj
__device__ float    g_cosr[SS*32];
__device__ float    g_sinr[SS*32];

// =====================================================================
// tf32 helpers
// =====================================================================
__device__ __forceinline__ uint32_t f2tf32(float f) {
    uint32_t r;
    asm("cvt.rna.tf32.f32 %0, %1;" : "=r"(r) : "f"(f));
    return r;
}

__device__ __forceinline__ void mma_tf32(float* c, const uint32_t* a,
                                         uint32_t b0, uint32_t b1) {
    asm volatile(
        "mma.sync.aligned.m16n8k8.row.col.f32.tf32.tf32.f32 "
        "{%0,%1,%2,%3}, {%4,%5,%6,%7}, {%8,%9}, {%0,%1,%2,%3};"
        : "+f"(c[0]), "+f"(c[1]), "+f"(c[2]), "+f"(c[3])
        : "r"(a[0]), "r"(a[1]), "r"(a[2]), "r"(a[3]), "r"(b0), "r"(b1));
}

__device__ __forceinline__ void cpa16(uint32_t dst, const void* src) {
    asm volatile("cp.async.cg.shared.global [%0], [%1], 16;"
                 :: "r"(dst), "l"(src));
}

// =====================================================================
// elementwise fp32 -> tf32 bits (plain layout)
// =====================================================================
__global__ void to_tf32(const float4* __restrict__ src,
                        uint4* __restrict__ dst, int n4)
{
    int i = blockIdx.x * blockDim.x + threadIdx.x;
    if (i < n4) {
        float4 v = src[i];
        dst[i] = make_uint4(f2tf32(v.x), f2tf32(v.y), f2tf32(v.z), f2tf32(v.w));
    }
}

// merged conversion of Wq|Wk|Wv into contiguous g_wt
__global__ void to_tf32_w3(const float4* __restrict__ wq,
                           const float4* __restrict__ wk,
                           const float4* __restrict__ wv,
                           uint4* __restrict__ dst)
{
    int i = blockIdx.x * blockDim.x + threadIdx.x;   // over QKVD*DIM/4
    const int nq = DIM * DIM / 4;
    const int nk = KVD * DIM / 4;
    float4 v;
    if (i < nq)            v = wq[i];
    else if (i < nq + nk)  v = wk[i - nq];
    else                   v = wv[i - nq - nk];
    dst[i] = make_uint4(f2tf32(v.x), f2tf32(v.y), f2tf32(v.z), f2tf32(v.w));
}

// =====================================================================
// warp-mma tf32 GEMM, CTA tile 256x128, 3-stage cp.async pipeline,
// REGISTER FRAGMENT DOUBLE-BUFFERING: fragments for k-step kc+1 load
// while kc's 32 HMMAs issue -> LDS latency hidden inside the warp.
// 256 threads (8 warps 4x2), warp tile 64x64, smem stride 36.
// stage = A 256x36 + B 128x36 = 13,824 words; 3 stages = 165,888 B.
// regs: acc 128 + frag 2x48 + ctrl ~ 212 (< 255, no spill).
// =====================================================================
#define SA 36
#define STG_W 13824
#define GEMM_SMEM_BYTES 165888

__global__ __launch_bounds__(256, 1)
void gemm_pre(const uint32_t* __restrict__ A, const uint32_t* __restrict__ W,
              float* __restrict__ C, int K, int ldc, int coloff)
{
    extern __shared__ uint32_t sm[];
    const int tid  = threadIdx.x;
    const int lane = tid & 31;
    const int wid  = tid >> 5;
    const int wm   = wid & 3;          // 0..3 -> 64-row slabs
    const int wn   = wid >> 2;         // 0..1 -> 64-col slabs
    const int g    = lane >> 2;
    const int t    = lane & 3;
    const int m0   = blockIdx.y * 256;
    const int n0   = blockIdx.x * 128;
    const uint32_t smb = (uint32_t)__cvta_generic_to_shared(sm);

    float acc[4][8][4];
#pragma unroll
    for (int mt = 0; mt < 4; mt++)
#pragma unroll
        for (int nt = 0; nt < 8; nt++)
#pragma unroll
            for (int c = 0; c < 4; c++) acc[mt][nt][c] = 0.f;

    const int ntile = K >> 5;

    auto load_tile = [&](int it, int s) {
        const uint32_t base = (uint32_t)s * STG_W;
        const size_t kb = (size_t)it * 32;
#pragma unroll
        for (int r = 0; r < 8; r++) {
            int id = tid + 256 * r;
            int row = id >> 3, c4 = (id & 7) * 4;
            cpa16(smb + (base + row * SA + c4) * 4,
                  A + (size_t)(m0 + row) * K + kb + c4);
        }
#pragma unroll
        for (int r = 0; r < 4; r++) {
            int id = tid + 256 * r;
            int row = id >> 3, c4 = (id & 7) * 4;
            cpa16(smb + (base + 9216 + row * SA + c4) * 4,
                  W + (size_t)(n0 + row) * K + kb + c4);
        }
        asm volatile("cp.async.commit_group;");
    };

    load_tile(0, 0);
    load_tile(1, 1);

    uint32_t af[2][4][4];   // [buf][mt][4]
    uint32_t bf[2][8][2];   // [buf][nt][2]

    int s = 0;
    for (int it = 0; it < ntile; it++) {
        if (it + 1 < ntile) {
            asm volatile("cp.async.wait_group 1;");
        } else {
            asm volatile("cp.async.wait_group 0;");
        }
        __syncthreads();

        if (it + 2 < ntile) {
            int s2 = s + 2; if (s2 >= 3) s2 -= 3;
            load_tile(it + 2, s2);
        }

        const uint32_t* As = sm + (uint32_t)s * STG_W;
        const uint32_t* Bs = As + 9216;

        // preload fragments for kc=0 into buffer 0
#pragma unroll
        for (int mt = 0; mt < 4; mt++) {
            int rb = wm * 64 + mt * 16;
            af[0][mt][0] = As[(rb + g    ) * SA + t    ];
            af[0][mt][1] = As[(rb + g + 8) * SA + t    ];
            af[0][mt][2] = As[(rb + g    ) * SA + t + 4];
            af[0][mt][3] = As[(rb + g + 8) * SA + t + 4];
        }
#pragma unroll
        for (int nt = 0; nt < 8; nt++) {
            int nb = wn * 64 + nt * 8 + g;
            bf[0][nt][0] = Bs[nb * SA + t    ];
            bf[0][nt][1] = Bs[nb * SA + t + 4];
        }

#pragma unroll
        for (int kc = 0; kc < 4; kc++) {
            const int cur = kc & 1;
            if (kc < 3) {
                const int kb = (kc + 1) * 8;
                const int nxt = cur ^ 1;
#pragma unroll
                for (int mt = 0; mt < 4; mt++) {
                    int rb = wm * 64 + mt * 16;
                    af[nxt][mt][0] = As[(rb + g    ) * SA + kb + t    ];
                    af[nxt][mt][1] = As[(rb + g + 8) * SA + kb + t    ];
                    af[nxt][mt][2] = As[(rb + g    ) * SA + kb + t + 4];
                    af[nxt][mt][3] = As[(rb + g + 8) * SA + kb + t + 4];
                }
#pragma unroll
                for (int nt = 0; nt < 8; nt++) {
                    int nb = wn * 64 + nt * 8 + g;
                    bf[nxt][nt][0] = Bs[nb * SA + kb + t    ];
                    bf[nxt][nt][1] = Bs[nb * SA + kb + t + 4];
                }
            }
#pragma unroll
            for (int nt = 0; nt < 8; nt++)
#pragma unroll
                for (int mt = 0; mt < 4; mt++)
                    mma_tf32(acc[mt][nt], af[cur][mt],
                             bf[cur][nt][0], bf[cur][nt][1]);
        }
        if (++s >= 3) s = 0;
    }

#pragma unroll
    for (int mt = 0; mt < 4; mt++) {
        int row = m0 + wm * 64 + mt * 16 + g;
#pragma unroll
        for (int nt = 0; nt < 8; nt++) {
            int col = coloff + n0 + wn * 64 + nt * 8 + 2 * t;
            float2 v01 = make_float2(acc[mt][nt][0], acc[mt][nt][1]);
            float2 v23 = make_float2(acc[mt][nt][2], acc[mt][nt][3]);
            *(float2*)(C + (size_t)row * ldc + col)       = v01;
            *(float2*)(C + (size_t)(row + 8) * ldc + col) = v23;
        }
    }
}

// =====================================================================
// RoPE table init
// =====================================================================
__global__ void rope_init()
{
    int i = blockIdx.x * blockDim.x + threadIdx.x;
    int s = i >> 5, f = i & 31;
    double inv = pow(10000.0, -(double)f / 32.0);
    double ang = (double)s * inv;
    double sd, cd;
    sincos(ang, &sd, &cd);
    g_cosr[i] = (float)cd;
    g_sinr[i] = (float)sd;
}

// =====================================================================
// RMS-norm + RoPE + gain + reshape; q/k/v stored as tf32 bits
// =====================================================================
__global__ void norm_rope(const float* __restrict__ qkv,
                          const float* __restrict__ q_gain,
                          float* __restrict__ q, float* __restrict__ k,
                          float* __restrict__ v)
{
    const int bs   = blockIdx.x;
    const int head = blockIdx.y;
    const int b = bs / SS, s = bs % SS;
    const int d = threadIdx.x;

    if (head >= NH + NKV) {
        int kv = head - NH - NKV;
        float val = qkv[(size_t)bs * QKVD + DIM + KVD + kv * HD + d];
        v[((size_t)(b * NKV + kv) * SS + s) * HD + d] = __uint_as_float(f2tf32(val));
        return;
    }
    const bool isq = (head < NH);
    const float* row = qkv + (size_t)bs * QKVD +
                       (isq ? head * HD : DIM + (head - NH) * HD);
    float val = row[d];

    __shared__ float red[4];
    __shared__ float xs[HD];
    float sq = val * val;
#pragma unroll
    for (int o = 16; o > 0; o >>= 1) sq += __shfl_xor_sync(0xffffffffu, sq, o);
    if ((d & 31) == 0) red[d >> 5] = sq;
    __syncthreads();
    float ms = (red[0] + red[1] + red[2] + red[3]) * (1.0f / HD);
    float xn = val * rsqrtf(ms + 1.1920929e-07f);
    xs[d] = xn;
    __syncthreads();

    float outv;
    if (d < 64) {
        int f = d & 31;
        float c  = g_cosr[s * 32 + f];
        float sn = g_sinr[s * 32 + f];
        float x1 = xs[f], x2 = xs[f + 32];
        outv = (d < 32) ? (x1 * c + x2 * sn) : (-x1 * sn + x2 * c);
    } else {
        outv = xn;
    }

    if (isq) {
        outv *= q_gain[head] * ATTN_SCALE;
        q[((size_t)(b * NH + head) * SS + s) * HD + d] = __uint_as_float(f2tf32(outv));
    } else {
        int kv = head - NH;
        k[((size_t)(b * NKV + kv) * SS + s) * HD + d] = __uint_as_float(f2tf32(outv));
    }
}

// =====================================================================
// tf32 flash attention (unchanged; epilogue emits plain tf32 y)
// =====================================================================
#define QS_OFF   0            // 128 x 132
#define KS_OFF   16896        // 64 x 132
#define VS_OFF0  25344        // 64 x 136
#define VS_OFF1  34048
#define PS_OFF   42752        // 128 x 68
#define PMAX_OFF 51456        // [2][128]
#define PSUM_OFF 51712        // [2][128]
#define MS_OFF   51968        // [128]
#define LS_OFF   52096        // [128]
#define ATTN_WORDS 52224      // 208,896 bytes

__global__ __launch_bounds__(256, 1)
void attn_mma(const float* __restrict__ q, const float* __restrict__ k,
              const float* __restrict__ v, uint32_t* __restrict__ y)
{
    extern __shared__ uint32_t sm[];
    const int qb = (int)gridDim.x - 1 - (int)blockIdx.x;
    const int h = blockIdx.y, b = blockIdx.z;
    const int kvh = h >> 2;
    const int tid = threadIdx.x;
    const int lane = tid & 31, wid = tid >> 5;
    const int g = lane >> 2, t = lane & 3;
    const int wm = wid & 3, wn = wid >> 2;
    const int bar_id = 1 + wm;

    const float* qbase = q + ((size_t)(b * NH + h) * SS + (size_t)qb * 128) * HD;
    const float* kbase = k + ((size_t)(b * NKV + kvh) * SS) * HD;
    const float* vbase = v + ((size_t)(b * NKV + kvh) * SS) * HD;

    const uint32_t smb = (uint32_t)__cvta_generic_to_shared(sm);

    float* m_s  = (float*)(sm + MS_OFF);
    float* l_s  = (float*)(sm + LS_OFF);
    float* pmax = (float*)(sm + PMAX_OFF);
    float* psum = (float*)(sm + PSUM_OFF);

#pragma unroll
    for (int i = 0; i < 16; i++) {
        int id = tid + 256 * i;
        int row = id >> 5, c4 = (id & 31) * 4;
        cpa16(smb + (QS_OFF + row * 132 + c4) * 4, qbase + (size_t)row * HD + c4);
    }
#pragma unroll
    for (int i = 0; i < 8; i++) {
        int id = tid + 256 * i;
        int row = id >> 5, c4 = (id & 31) * 4;
        cpa16(smb + (KS_OFF + row * 132 + c4) * 4, kbase + (size_t)row * HD + c4);
        cpa16(smb + (VS_OFF0 + row * 136 + c4) * 4, vbase + (size_t)row * HD + c4);
    }
    asm volatile("cp.async.commit_group;");

    if (tid < 128) { m_s[tid] = -1e30f; l_s[tid] = 0.f; }

    float oacc[2][8][4];
#pragma unroll
    for (int mt = 0; mt < 2; mt++)
#pragma unroll
        for (int nt = 0; nt < 8; nt++)
#pragma unroll
            for (int c = 0; c < 4; c++) oacc[mt][nt][c] = 0.f;

    const int nkv = 2 * qb + 2;

    asm volatile("cp.async.wait_group 0;");
    __syncthreads();

    for (int kvt = 0; kvt < nkv; kvt++) {
        const int cur = kvt & 1;

        float sacc[2][4][4];
#pragma unroll
        for (int mt = 0; mt < 2; mt++)
#pragma unroll
            for (int nt = 0; nt < 4; nt++)
#pragma unroll
                for (int c = 0; c < 4; c++) sacc[mt][nt][c] = 0.f;

        const uint32_t* Qb = sm + QS_OFF + (wm * 32) * 132;
        const uint32_t* Kb = sm + KS_OFF + (wn * 32) * 132;
#pragma unroll
        for (int ks = 0; ks < 16; ks++) {
            const int kb = ks * 8;
            uint32_t a[2][4];
#pragma unroll
            for (int mt = 0; mt < 2; mt++) {
                const uint32_t* Qr = Qb + mt * 16 * 132;
                a[mt][0] = Qr[g * 132 + kb + t];
                a[mt][1] = Qr[(g + 8) * 132 + kb + t];
                a[mt][2] = Qr[g * 132 + kb + t + 4];
                a[mt][3] = Qr[(g + 8) * 132 + kb + t + 4];
            }
#pragma unroll
            for (int nt = 0; nt < 4; nt++) {
                uint32_t b0 = Kb[(nt * 8 + g) * 132 + kb + t];
                uint32_t b1 = Kb[(nt * 8 + g) * 132 + kb + t + 4];
                mma_tf32(sacc[0][nt], a[0], b0, b1);
                mma_tf32(sacc[1][nt], a[1], b0, b1);
            }
        }

        if (kvt >= 2 * qb) {
            const int off = (kvt - 2 * qb) * 64;
#pragma unroll
            for (int mt = 0; mt < 2; mt++) {
                int r0 = wm * 32 + mt * 16 + g, r1 = r0 + 8;
#pragma unroll
                for (int nt = 0; nt < 4; nt++) {
                    int c = wn * 32 + nt * 8 + 2 * t + off;
                    if (c     > r0) sacc[mt][nt][0] = -1e30f;
                    if (c + 1 > r0) sacc[mt][nt][1] = -1e30f;
                    if (c     > r1) sacc[mt][nt][2] = -1e30f;
                    if (c + 1 > r1) sacc[mt][nt][3] = -1e30f;
                }
            }
        }

#pragma unroll
        for (int mt = 0; mt < 2; mt++) {
            float rm0 = -1e30f, rm1 = -1e30f;
#pragma unroll
            for (int nt = 0; nt < 4; nt++) {
                rm0 = fmaxf(rm0, fmaxf(sacc[mt][nt][0], sacc[mt][nt][1]));
                rm1 = fmaxf(rm1, fmaxf(sacc[mt][nt][2], sacc[mt][nt][3]));
            }
            rm0 = fmaxf(rm0, __shfl_xor_sync(0xffffffffu, rm0, 1));
            rm0 = fmaxf(rm0, __shfl_xor_sync(0xffffffffu, rm0, 2));
            rm1 = fmaxf(rm1, __shfl_xor_sync(0xffffffffu, rm1, 1));
            rm1 = fmaxf(rm1, __shfl_xor_sync(0xffffffffu, rm1, 2));
            if (t == 0) {
                pmax[wn * 128 + wm * 32 + mt * 16 + g]     = rm0;
                pmax[wn * 128 + wm * 32 + mt * 16 + g + 8] = rm1;
            }
        }
        asm volatile("bar.sync %0, 64;" :: "r"(bar_id) : "memory");

        float alpha[2][2], mnew[2][2];
#pragma unroll
        for (int mt = 0; mt < 2; mt++) {
            int r0 = wm * 32 + mt * 16 + g, r1 = r0 + 8;
            float mo0 = m_s[r0], mo1 = m_s[r1];
            float mn0 = fmaxf(mo0, fmaxf(pmax[r0], pmax[128 + r0]));
            float mn1 = fmaxf(mo1, fmaxf(pmax[r1], pmax[128 + r1]));
            alpha[mt][0] = __expf(mo0 - mn0);
            alpha[mt][1] = __expf(mo1 - mn1);
            mnew[mt][0] = mn0; mnew[mt][1] = mn1;
            float rs0 = 0.f, rs1 = 0.f;
#pragma unroll
            for (int nt = 0; nt < 4; nt++) {
                float p00 = __expf(sacc[mt][nt][0] - mn0);
                float p01 = __expf(sacc[mt][nt][1] - mn0);
                float p10 = __expf(sacc[mt][nt][2] - mn1);
                float p11 = __expf(sacc[mt][nt][3] - mn1);
                rs0 += p00 + p01;
                rs1 += p10 + p11;
                int col = wn * 32 + nt * 8 + 2 * t;
                *(uint2*)(sm + PS_OFF + r0 * 68 + col) = make_uint2(f2tf32(p00), f2tf32(p01));
                *(uint2*)(sm + PS_OFF + r1 * 68 + col) = make_uint2(f2tf32(p10), f2tf32(p11));
            }
            rs0 += __shfl_xor_sync(0xffffffffu, rs0, 1);
            rs0 += __shfl_xor_sync(0xffffffffu, rs0, 2);
            rs1 += __shfl_xor_sync(0xffffffffu, rs1, 1);
            rs1 += __shfl_xor_sync(0xffffffffu, rs1, 2);
            if (t == 0) {
                psum[wn * 128 + r0] = rs0;
                psum[wn * 128 + r1] = rs1;
            }
        }
#pragma unroll
        for (int mt = 0; mt < 2; mt++)
#pragma unroll
            for (int nt = 0; nt < 8; nt++) {
                oacc[mt][nt][0] *= alpha[mt][0];
                oacc[mt][nt][1] *= alpha[mt][0];
                oacc[mt][nt][2] *= alpha[mt][1];
                oacc[mt][nt][3] *= alpha[mt][1];
            }
        asm volatile("bar.sync %0, 64;" :: "r"(bar_id) : "memory");
        if (wn == 0 && t == 0) {
#pragma unroll
            for (int mt = 0; mt < 2; mt++) {
                int r0 = wm * 32 + mt * 16 + g, r1 = r0 + 8;
                l_s[r0] = l_s[r0] * alpha[mt][0] + psum[r0] + psum[128 + r0];
                l_s[r1] = l_s[r1] * alpha[mt][1] + psum[r1] + psum[128 + r1];
                m_s[r0] = mnew[mt][0];
                m_s[r1] = mnew[mt][1];
            }
        }

        __syncthreads();
        if (kvt + 1 < nkv) {
            const float* kn = kbase + (size_t)(kvt + 1) * 64 * HD;
            const float* vn = vbase + (size_t)(kvt + 1) * 64 * HD;
            const uint32_t vo = cur ? VS_OFF0 : VS_OFF1;
#pragma unroll
            for (int i = 0; i < 8; i++) {
                int id = tid + 256 * i;
                int row = id >> 5, c4 = (id & 31) * 4;
                cpa16(smb + (KS_OFF + row * 132 + c4) * 4, kn + (size_t)row * HD + c4);
                cpa16(smb + (vo + row * 136 + c4) * 4, vn + (size_t)row * HD + c4);
            }
            asm volatile("cp.async.commit_group;");
        }

        const uint32_t* Pb = sm + PS_OFF + (wm * 32) * 68;
        const uint32_t* Vb = sm + (cur ? VS_OFF1 : VS_OFF0) + wn * 64;
#pragma unroll
        for (int ks = 0; ks < 8; ks++) {
            const int kb = ks * 8;
            uint32_t a[2][4];
#pragma unroll
            for (int mt = 0; mt < 2; mt++) {
                const uint32_t* Pr = Pb + mt * 16 * 68;
                a[mt][0] = Pr[g * 68 + kb + t];
                a[mt][1] = Pr[(g + 8) * 68 + kb + t];
                a[mt][2] = Pr[g * 68 + kb + t + 4];
                a[mt][3] = Pr[(g + 8) * 68 + kb + t + 4];
            }
#pragma unroll
            for (int nt = 0; nt < 8; nt++) {
                uint32_t b0 = Vb[(kb + t) * 136 + nt * 8 + g];
                uint32_t b1 = Vb[(kb + t + 4) * 136 + nt * 8 + g];
                mma_tf32(oacc[0][nt], a[0], b0, b1);
                mma_tf32(oacc[1][nt], a[1], b0, b1);
            }
        }

        if (kvt + 1 < nkv) {
            asm volatile("cp.async.wait_group 0;");
            __syncthreads();
        }
    }

    asm volatile("bar.sync %0, 64;" :: "r"(bar_id) : "memory");

#pragma unroll
    for (int mt = 0; mt < 2; mt++) {
        int r0 = wm * 32 + mt * 16 + g, r1 = r0 + 8;
        float linv0 = 1.0f / l_s[r0];
        float linv1 = 1.0f / l_s[r1];
        uint32_t* y0 = y + ((size_t)b * SS + (size_t)qb * 128 + r0) * DIM + h * HD + wn * 64;
        uint32_t* y1 = y + ((size_t)b * SS + (size_t)qb * 128 + r1) * DIM + h * HD + wn * 64;
#pragma unroll
        for (int nt = 0; nt < 8; nt++) {
            int col = nt * 8 + 2 * t;
            *(uint2*)(y0 + col) = make_uint2(f2tf32(oacc[mt][nt][0] * linv0),
                                             f2tf32(oacc[mt][nt][1] * linv0));
            *(uint2*)(y1 + col) = make_uint2(f2tf32(oacc[mt][nt][2] * linv1),
                                             f2tf32(oacc[mt][nt][3] * linv1));
        }
    }
}

// =====================================================================
// host
// =====================================================================
extern "C" void kernel_launch(void* const* d_in, const int* in_sizes, int n_in,
                              void* d_out, int out_size)
{
    const float* x     = (const float*)d_in[0];
    const float* Wq    = (const float*)d_in[1];
    const float* Wk    = (const float*)d_in[2];
    const float* Wv    = (const float*)d_in[3];
    const float* Wproj = (const float*)d_in[4];
    const float* qg    = (const float*)d_in[5];
    float* out = (float*)d_out;

    float *qkv, *q, *k, *v;
    uint32_t *y, *xt, *wt, *wpt;
    cudaGetSymbolAddress((void**)&qkv, g_qkv);
    cudaGetSymbolAddress((void**)&q,   g_q);
    cudaGetSymbolAddress((void**)&k,   g_k);
    cudaGetSymbolAddress((void**)&v,   g_v);
    cudaGetSymbolAddress((void**)&y,   g_y);
    cudaGetSymbolAddress((void**)&xt,  g_xt);
    cudaGetSymbolAddress((void**)&wt,  g_wt);
    cudaGetSymbolAddress((void**)&wpt, g_wpt);

    cudaFuncSetAttribute(attn_mma,
                         cudaFuncAttributeMaxDynamicSharedMemorySize,
                         ATTN_WORDS * sizeof(uint32_t));
    cudaFuncSetAttribute(gemm_pre,
                         cudaFuncAttributeMaxDynamicSharedMemorySize,
                         GEMM_SMEM_BYTES);

    // (0) RoPE tables
    rope_init<<<SS * 32 / 256, 256>>>();
    // (1) convert x
    to_tf32<<<(MROWS * DIM / 4 + 255) / 256, 256>>>((const float4*)x, (uint4*)xt, MROWS * DIM / 4);
    // (2) convert Wq|Wk|Wv (one launch)
    to_tf32_w3<<<(QKVD * DIM / 4) / 256, 256>>>(
        (const float4*)Wq, (const float4*)Wk, (const float4*)Wv, (uint4*)wt);

    // (3) merged QKV projection  <-- ncu lands here (launch index 3)
    gemm_pre<<<dim3(QKVD / 128, MROWS / 256), 256, GEMM_SMEM_BYTES>>>(
        xt, wt, qkv, DIM, QKVD, 0);

    // (4) RMS-norm + RoPE + gain + reshape (tf32 outputs)
    norm_rope<<<dim3(BB * SS, NH + 2 * NKV), 128>>>(qkv, qg, q, k, v);

    // (5) flash attention -> g_y (tf32 bits)
    attn_mma<<<dim3(SS / 128, NH, BB), 256,
               ATTN_WORDS * sizeof(uint32_t)>>>(q, k, v, y);

    // (6) convert Wproj
    to_tf32<<<(DIM * DIM / 4 + 255) / 256, 256>>>((const float4*)Wproj, (uint4*)wpt, DIM * DIM / 4);

    // (7) output projection
    gemm_pre<<<dim3(DIM / 128, MROWS / 256), 256, GEMM_SMEM_BYTES>>>(
        y, wpt, out, DIM, DIM, 0);
}

// round 12
// speedup vs baseline: 1.4267x; 1.4267x over previous
#include <cuda_runtime.h>
#include <cuda_fp16.h>
#include <math.h>
#include <stdint.h>

#define DIM 2048
#define NH 16
#define NKV 4
#define HD 128
#define BB 4
#define SS 2048
#define KVD 512        // NKV*HD
#define QKVD 3072      // DIM + 2*KVD
#define MROWS (BB*SS)  // 8192
#define ATTN_SCALE 0.08838834764831845f  // 1/sqrt(128)

// ---------------- scratch (no allocations allowed) ----------------
__device__ float    g_qkv[(size_t)BB*SS*QKVD];     // fp32 gemm outputs
__device__ float    g_q[(size_t)BB*NH*SS*HD];      // tf32 bits (scale folded)
__device__ float    g_k[(size_t)BB*NKV*SS*HD];     // tf32 bits
__device__ float    g_v[(size_t)BB*NKV*SS*HD];     // tf32 bits
__device__ uint32_t g_y[(size_t)BB*SS*DIM/2];      // fp16x2 (attn out)
__device__ uint32_t g_xt[(size_t)MROWS*DIM/2];     // fp16x2 of x
__device__ uint32_t g_wt[(size_t)QKVD*DIM/2];      // fp16x2 Wq|Wk|Wv
__device__ uint32_t g_wpt[(size_t)DIM*DIM/2];      // fp16x2 Wproj
__device__ float    g_cosr[SS*32];
__device__ float    g_sinr[SS*32];

// =====================================================================
// helpers
// =====================================================================
__device__ __forceinline__ uint32_t f2tf32(float f) {
    uint32_t r;
    asm("cvt.rna.tf32.f32 %0, %1;" : "=r"(r) : "f"(f));
    return r;
}

__device__ __forceinline__ void mma_tf32(float* c, const uint32_t* a,
                                         uint32_t b0, uint32_t b1) {
    asm volatile(
        "mma.sync.aligned.m16n8k8.row.col.f32.tf32.tf32.f32 "
        "{%0,%1,%2,%3}, {%4,%5,%6,%7}, {%8,%9}, {%0,%1,%2,%3};"
        : "+f"(c[0]), "+f"(c[1]), "+f"(c[2]), "+f"(c[3])
        : "r"(a[0]), "r"(a[1]), "r"(a[2]), "r"(a[3]), "r"(b0), "r"(b1));
}

__device__ __forceinline__ void mma_fp16(float* c, const uint32_t* a,
                                         uint32_t b0, uint32_t b1) {
    asm volatile(
        "mma.sync.aligned.m16n8k16.row.col.f32.f16.f16.f32 "
        "{%0,%1,%2,%3}, {%4,%5,%6,%7}, {%8,%9}, {%0,%1,%2,%3};"
        : "+f"(c[0]), "+f"(c[1]), "+f"(c[2]), "+f"(c[3])
        : "r"(a[0]), "r"(a[1]), "r"(a[2]), "r"(a[3]), "r"(b0), "r"(b1));
}

__device__ __forceinline__ void cpa16(uint32_t dst, const void* src) {
    asm volatile("cp.async.cg.shared.global [%0], [%1], 16;"
                 :: "r"(dst), "l"(src));
}

__device__ __forceinline__ uint32_t pack_h2(float x, float y) {
    __half2 h = __floats2half2_rn(x, y);
    return *(uint32_t*)&h;
}

// =====================================================================
// elementwise fp32 -> fp16x2 conversions
// =====================================================================
__global__ void to_fp16(const float4* __restrict__ src,
                        uint2* __restrict__ dst, int n4)
{
    int i = blockIdx.x * blockDim.x + threadIdx.x;
    if (i < n4) {
        float4 v = src[i];
        dst[i] = make_uint2(pack_h2(v.x, v.y), pack_h2(v.z, v.w));
    }
}

// merged conversion of Wq|Wk|Wv into contiguous g_wt
__global__ void to_fp16_w3(const float4* __restrict__ wq,
                           const float4* __restrict__ wk,
                           const float4* __restrict__ wv,
                           uint2* __restrict__ dst)
{
    int i = blockIdx.x * blockDim.x + threadIdx.x;   // over QKVD*DIM/4
    const int nq = DIM * DIM / 4;
    const int nk = KVD * DIM / 4;
    float4 v;
    if (i < nq)            v = wq[i];
    else if (i < nq + nk)  v = wk[i - nq];
    else                   v = wv[i - nq - nk];
    dst[i] = make_uint2(pack_h2(v.x, v.y), pack_h2(v.z, v.w));
}

// =====================================================================
// fp16 warp-mma GEMM (fp32 accumulate). C[m,coloff+n] = sum A[m,k]W[n,k].
// 128x128x32 CTA tile, 3-stage cp.async, 8 warps (4x2), warp 32x64,
// m16n8k16. Smem rows: 16 words (32 halfs) padded to 20 -> conflict-free
// (20g+t distinct mod 32). stage = 2x128x20 = 5120 words; 3 stages
// = 61,440 B; 2 CTAs/SM.
// =====================================================================
#define SH 20
#define STG_W 5120
#define GEMM_SMEM_BYTES 61440

__global__ __launch_bounds__(256, 2)
void gemm_fp16(const uint32_t* __restrict__ A, const uint32_t* __restrict__ W,
               float* __restrict__ C, int K, int ldc, int coloff)
{
    extern __shared__ uint32_t sm[];
    const int KW   = K >> 1;           // words per row
    const int tid  = threadIdx.x;
    const int lane = tid & 31;
    const int wid  = tid >> 5;
    const int wm   = wid & 3;          // 0..3 -> 32-row slabs
    const int wn   = wid >> 2;         // 0..1 -> 64-col slabs
    const int g    = lane >> 2;
    const int t    = lane & 3;
    const int m0   = blockIdx.y * 128;
    const int n0   = blockIdx.x * 128;
    const uint32_t smb = (uint32_t)__cvta_generic_to_shared(sm);

    float acc[2][8][4];
#pragma unroll
    for (int mt = 0; mt < 2; mt++)
#pragma unroll
        for (int nt = 0; nt < 8; nt++)
#pragma unroll
            for (int c = 0; c < 4; c++) acc[mt][nt][c] = 0.f;

    const int ntile = K >> 5;          // 32 k-elements (16 words) per tile

    auto load_tile = [&](int it, int s) {
        const uint32_t base = (uint32_t)s * STG_W;
        const size_t kwb = (size_t)it * 16;
        // A: 128 rows x 16 words = 512 cpa16 (2/thread); B same
#pragma unroll
        for (int r = 0; r < 2; r++) {
            int id = tid + 256 * r;
            int row = id >> 2, c4 = (id & 3) * 4;
            cpa16(smb + (base + row * SH + c4) * 4,
                  A + (size_t)(m0 + row) * KW + kwb + c4);
            cpa16(smb + (base + 2560 + row * SH + c4) * 4,
                  W + (size_t)(n0 + row) * KW + kwb + c4);
        }
        asm volatile("cp.async.commit_group;");
    };

    load_tile(0, 0);
    load_tile(1, 1);

    int s = 0;
    for (int it = 0; it < ntile; it++) {
        if (it + 1 < ntile) {
            asm volatile("cp.async.wait_group 1;");
        } else {
            asm volatile("cp.async.wait_group 0;");
        }
        __syncthreads();

        if (it + 2 < ntile) {
            int s2 = s + 2; if (s2 >= 3) s2 -= 3;
            load_tile(it + 2, s2);
        }

        const uint32_t* As = sm + (uint32_t)s * STG_W;
        const uint32_t* Bs = As + 2560;
#pragma unroll
        for (int h = 0; h < 2; h++) {          // two k16 steps per tile
            const int base = h * 8;
            uint32_t a[2][4];
#pragma unroll
            for (int mt = 0; mt < 2; mt++) {
                int rb = wm * 32 + mt * 16;
                a[mt][0] = As[(rb + g    ) * SH + base + t    ];
                a[mt][1] = As[(rb + g + 8) * SH + base + t    ];
                a[mt][2] = As[(rb + g    ) * SH + base + t + 4];
                a[mt][3] = As[(rb + g + 8) * SH + base + t + 4];
            }
#pragma unroll
            for (int nt = 0; nt < 8; nt++) {
                int nb = wn * 64 + nt * 8 + g;
                uint32_t b0 = Bs[nb * SH + base + t    ];
                uint32_t b1 = Bs[nb * SH + base + t + 4];
                mma_fp16(acc[0][nt], a[0], b0, b1);
                mma_fp16(acc[1][nt], a[1], b0, b1);
            }
        }
        if (++s >= 3) s = 0;
    }

#pragma unroll
    for (int mt = 0; mt < 2; mt++) {
        int row = m0 + wm * 32 + mt * 16 + g;
#pragma unroll
        for (int nt = 0; nt < 8; nt++) {
            int col = coloff + n0 + wn * 64 + nt * 8 + 2 * t;
            float2 v01 = make_float2(acc[mt][nt][0], acc[mt][nt][1]);
            float2 v23 = make_float2(acc[mt][nt][2], acc[mt][nt][3]);
            *(float2*)(C + (size_t)row * ldc + col)       = v01;
            *(float2*)(C + (size_t)(row + 8) * ldc + col) = v23;
        }
    }
}

// =====================================================================
// RoPE table init
// =====================================================================
__global__ void rope_init()
{
    int i = blockIdx.x * blockDim.x + threadIdx.x;
    int s = i >> 5, f = i & 31;
    double inv = pow(10000.0, -(double)f / 32.0);
    double ang = (double)s * inv;
    double sd, cd;
    sincos(ang, &sd, &cd);
    g_cosr[i] = (float)cd;
    g_sinr[i] = (float)sd;
}

// =====================================================================
// RMS-norm + RoPE + gain + reshape; q/k/v stored as tf32 bits
// =====================================================================
__global__ void norm_rope(const float* __restrict__ qkv,
                          const float* __restrict__ q_gain,
                          float* __restrict__ q, float* __restrict__ k,
                          float* __restrict__ v)
{
    const int bs   = blockIdx.x;
    const int head = blockIdx.y;
    const int b = bs / SS, s = bs % SS;
    const int d = threadIdx.x;

    if (head >= NH + NKV) {
        int kv = head - NH - NKV;
        float val = qkv[(size_t)bs * QKVD + DIM + KVD + kv * HD + d];
        v[((size_t)(b * NKV + kv) * SS + s) * HD + d] = __uint_as_float(f2tf32(val));
        return;
    }
    const bool isq = (head < NH);
    const float* row = qkv + (size_t)bs * QKVD +
                       (isq ? head * HD : DIM + (head - NH) * HD);
    float val = row[d];

    __shared__ float red[4];
    __shared__ float xs[HD];
    float sq = val * val;
#pragma unroll
    for (int o = 16; o > 0; o >>= 1) sq += __shfl_xor_sync(0xffffffffu, sq, o);
    if ((d & 31) == 0) red[d >> 5] = sq;
    __syncthreads();
    float ms = (red[0] + red[1] + red[2] + red[3]) * (1.0f / HD);
    float xn = val * rsqrtf(ms + 1.1920929e-07f);
    xs[d] = xn;
    __syncthreads();

    float outv;
    if (d < 64) {
        int f = d & 31;
        float c  = g_cosr[s * 32 + f];
        float sn = g_sinr[s * 32 + f];
        float x1 = xs[f], x2 = xs[f + 32];
        outv = (d < 32) ? (x1 * c + x2 * sn) : (-x1 * sn + x2 * c);
    } else {
        outv = xn;
    }

    if (isq) {
        outv *= q_gain[head] * ATTN_SCALE;
        q[((size_t)(b * NH + head) * SS + s) * HD + d] = __uint_as_float(f2tf32(outv));
    } else {
        int kv = head - NH;
        k[((size_t)(b * NKV + kv) * SS + s) * HD + d] = __uint_as_float(f2tf32(outv));
    }
}

// =====================================================================
// tf32 flash attention (unchanged compute; epilogue emits fp16x2 y)
// =====================================================================
#define QS_OFF   0            // 128 x 132
#define KS_OFF   16896        // 64 x 132
#define VS_OFF0  25344        // 64 x 136
#define VS_OFF1  34048
#define PS_OFF   42752        // 128 x 68
#define PMAX_OFF 51456        // [2][128]
#define PSUM_OFF 51712        // [2][128]
#define MS_OFF   51968        // [128]
#define LS_OFF   52096        // [128]
#define ATTN_WORDS 52224      // 208,896 bytes

__global__ __launch_bounds__(256, 1)
void attn_mma(const float* __restrict__ q, const float* __restrict__ k,
              const float* __restrict__ v, uint32_t* __restrict__ y)
{
    extern __shared__ uint32_t sm[];
    const int qb = (int)gridDim.x - 1 - (int)blockIdx.x;
    const int h = blockIdx.y, b = blockIdx.z;
    const int kvh = h >> 2;
    const int tid = threadIdx.x;
    const int lane = tid & 31, wid = tid >> 5;
    const int g = lane >> 2, t = lane & 3;
    const int wm = wid & 3, wn = wid >> 2;
    const int bar_id = 1 + wm;

    const float* qbase = q + ((size_t)(b * NH + h) * SS + (size_t)qb * 128) * HD;
    const float* kbase = k + ((size_t)(b * NKV + kvh) * SS) * HD;
    const float* vbase = v + ((size_t)(b * NKV + kvh) * SS) * HD;

    const uint32_t smb = (uint32_t)__cvta_generic_to_shared(sm);

    float* m_s  = (float*)(sm + MS_OFF);
    float* l_s  = (float*)(sm + LS_OFF);
    float* pmax = (float*)(sm + PMAX_OFF);
    float* psum = (float*)(sm + PSUM_OFF);

#pragma unroll
    for (int i = 0; i < 16; i++) {
        int id = tid + 256 * i;
        int row = id >> 5, c4 = (id & 31) * 4;
        cpa16(smb + (QS_OFF + row * 132 + c4) * 4, qbase + (size_t)row * HD + c4);
    }
#pragma unroll
    for (int i = 0; i < 8; i++) {
        int id = tid + 256 * i;
        int row = id >> 5, c4 = (id & 31) * 4;
        cpa16(smb + (KS_OFF + row * 132 + c4) * 4, kbase + (size_t)row * HD + c4);
        cpa16(smb + (VS_OFF0 + row * 136 + c4) * 4, vbase + (size_t)row * HD + c4);
    }
    asm volatile("cp.async.commit_group;");

    if (tid < 128) { m_s[tid] = -1e30f; l_s[tid] = 0.f; }

    float oacc[2][8][4];
#pragma unroll
    for (int mt = 0; mt < 2; mt++)
#pragma unroll
        for (int nt = 0; nt < 8; nt++)
#pragma unroll
            for (int c = 0; c < 4; c++) oacc[mt][nt][c] = 0.f;

    const int nkv = 2 * qb + 2;

    asm volatile("cp.async.wait_group 0;");
    __syncthreads();

    for (int kvt = 0; kvt < nkv; kvt++) {
        const int cur = kvt & 1;

        float sacc[2][4][4];
#pragma unroll
        for (int mt = 0; mt < 2; mt++)
#pragma unroll
            for (int nt = 0; nt < 4; nt++)
#pragma unroll
                for (int c = 0; c < 4; c++) sacc[mt][nt][c] = 0.f;

        const uint32_t* Qb = sm + QS_OFF + (wm * 32) * 132;
        const uint32_t* Kb = sm + KS_OFF + (wn * 32) * 132;
#pragma unroll
        for (int ks = 0; ks < 16; ks++) {
            const int kb = ks * 8;
            uint32_t a[2][4];
#pragma unroll
            for (int mt = 0; mt < 2; mt++) {
                const uint32_t* Qr = Qb + mt * 16 * 132;
                a[mt][0] = Qr[g * 132 + kb + t];
                a[mt][1] = Qr[(g + 8) * 132 + kb + t];
                a[mt][2] = Qr[g * 132 + kb + t + 4];
                a[mt][3] = Qr[(g + 8) * 132 + kb + t + 4];
            }
#pragma unroll
            for (int nt = 0; nt < 4; nt++) {
                uint32_t b0 = Kb[(nt * 8 + g) * 132 + kb + t];
                uint32_t b1 = Kb[(nt * 8 + g) * 132 + kb + t + 4];
                mma_tf32(sacc[0][nt], a[0], b0, b1);
                mma_tf32(sacc[1][nt], a[1], b0, b1);
            }
        }

        if (kvt >= 2 * qb) {
            const int off = (kvt - 2 * qb) * 64;
#pragma unroll
            for (int mt = 0; mt < 2; mt++) {
                int r0 = wm * 32 + mt * 16 + g, r1 = r0 + 8;
#pragma unroll
                for (int nt = 0; nt < 4; nt++) {
                    int c = wn * 32 + nt * 8 + 2 * t + off;
                    if (c     > r0) sacc[mt][nt][0] = -1e30f;
                    if (c + 1 > r0) sacc[mt][nt][1] = -1e30f;
                    if (c     > r1) sacc[mt][nt][2] = -1e30f;
                    if (c + 1 > r1) sacc[mt][nt][3] = -1e30f;
                }
            }
        }

#pragma unroll
        for (int mt = 0; mt < 2; mt++) {
            float rm0 = -1e30f, rm1 = -1e30f;
#pragma unroll
            for (int nt = 0; nt < 4; nt++) {
                rm0 = fmaxf(rm0, fmaxf(sacc[mt][nt][0], sacc[mt][nt][1]));
                rm1 = fmaxf(rm1, fmaxf(sacc[mt][nt][2], sacc[mt][nt][3]));
            }
            rm0 = fmaxf(rm0, __shfl_xor_sync(0xffffffffu, rm0, 1));
            rm0 = fmaxf(rm0, __shfl_xor_sync(0xffffffffu, rm0, 2));
            rm1 = fmaxf(rm1, __shfl_xor_sync(0xffffffffu, rm1, 1));
            rm1 = fmaxf(rm1, __shfl_xor_sync(0xffffffffu, rm1, 2));
            if (t == 0) {
                pmax[wn * 128 + wm * 32 + mt * 16 + g]     = rm0;
                pmax[wn * 128 + wm * 32 + mt * 16 + g + 8] = rm1;
            }
        }
        asm volatile("bar.sync %0, 64;" :: "r"(bar_id) : "memory");

        float alpha[2][2], mnew[2][2];
#pragma unroll
        for (int mt = 0; mt < 2; mt++) {
            int r0 = wm * 32 + mt * 16 + g, r1 = r0 + 8;
            float mo0 = m_s[r0], mo1 = m_s[r1];
            float mn0 = fmaxf(mo0, fmaxf(pmax[r0], pmax[128 + r0]));
            float mn1 = fmaxf(mo1, fmaxf(pmax[r1], pmax[128 + r1]));
            alpha[mt][0] = __expf(mo0 - mn0);
            alpha[mt][1] = __expf(mo1 - mn1);
            mnew[mt][0] = mn0; mnew[mt][1] = mn1;
            float rs0 = 0.f, rs1 = 0.f;
#pragma unroll
            for (int nt = 0; nt < 4; nt++) {
                float p00 = __expf(sacc[mt][nt][0] - mn0);
                float p01 = __expf(sacc[mt][nt][1] - mn0);
                float p10 = __expf(sacc[mt][nt][2] - mn1);
                float p11 = __expf(sacc[mt][nt][3] - mn1);
                rs0 += p00 + p01;
                rs1 += p10 + p11;
                int col = wn * 32 + nt * 8 + 2 * t;
                *(uint2*)(sm + PS_OFF + r0 * 68 + col) = make_uint2(f2tf32(p00), f2tf32(p01));
                *(uint2*)(sm + PS_OFF + r1 * 68 + col) = make_uint2(f2tf32(p10), f2tf32(p11));
            }
            rs0 += __shfl_xor_sync(0xffffffffu, rs0, 1);
            rs0 += __shfl_xor_sync(0xffffffffu, rs0, 2);
            rs1 += __shfl_xor_sync(0xffffffffu, rs1, 1);
            rs1 += __shfl_xor_sync(0xffffffffu, rs1, 2);
            if (t == 0) {
                psum[wn * 128 + r0] = rs0;
                psum[wn * 128 + r1] = rs1;
            }
        }
#pragma unroll
        for (int mt = 0; mt < 2; mt++)
#pragma unroll
            for (int nt = 0; nt < 8; nt++) {
                oacc[mt][nt][0] *= alpha[mt][0];
                oacc[mt][nt][1] *= alpha[mt][0];
                oacc[mt][nt][2] *= alpha[mt][1];
                oacc[mt][nt][3] *= alpha[mt][1];
            }
        asm volatile("bar.sync %0, 64;" :: "r"(bar_id) : "memory");
        if (wn == 0 && t == 0) {
#pragma unroll
            for (int mt = 0; mt < 2; mt++) {
                int r0 = wm * 32 + mt * 16 + g, r1 = r0 + 8;
                l_s[r0] = l_s[r0] * alpha[mt][0] + psum[r0] + psum[128 + r0];
                l_s[r1] = l_s[r1] * alpha[mt][1] + psum[r1] + psum[128 + r1];
                m_s[r0] = mnew[mt][0];
                m_s[r1] = mnew[mt][1];
            }
        }

        __syncthreads();
        if (kvt + 1 < nkv) {
            const float* kn = kbase + (size_t)(kvt + 1) * 64 * HD;
            const float* vn = vbase + (size_t)(kvt + 1) * 64 * HD;
            const uint32_t vo = cur ? VS_OFF0 : VS_OFF1;
#pragma unroll
            for (int i = 0; i < 8; i++) {
                int id = tid + 256 * i;
                int row = id >> 5, c4 = (id & 31) * 4;
                cpa16(smb + (KS_OFF + row * 132 + c4) * 4, kn + (size_t)row * HD + c4);
                cpa16(smb + (vo + row * 136 + c4) * 4, vn + (size_t)row * HD + c4);
            }
            asm volatile("cp.async.commit_group;");
        }

        const uint32_t* Pb = sm + PS_OFF + (wm * 32) * 68;
        const uint32_t* Vb = sm + (cur ? VS_OFF1 : VS_OFF0) + wn * 64;
#pragma unroll
        for (int ks = 0; ks < 8; ks++) {
            const int kb = ks * 8;
            uint32_t a[2][4];
#pragma unroll
            for (int mt = 0; mt < 2; mt++) {
                const uint32_t* Pr = Pb + mt * 16 * 68;
                a[mt][0] = Pr[g * 68 + kb + t];
                a[mt][1] = Pr[(g + 8) * 68 + kb + t];
                a[mt][2] = Pr[g * 68 + kb + t + 4];
                a[mt][3] = Pr[(g + 8) * 68 + kb + t + 4];
            }
#pragma unroll
            for (int nt = 0; nt < 8; nt++) {
                uint32_t b0 = Vb[(kb + t) * 136 + nt * 8 + g];
                uint32_t b1 = Vb[(kb + t + 4) * 136 + nt * 8 + g];
                mma_tf32(oacc[0][nt], a[0], b0, b1);
                mma_tf32(oacc[1][nt], a[1], b0, b1);
            }
        }

        if (kvt + 1 < nkv) {
            asm volatile("cp.async.wait_group 0;");
            __syncthreads();
        }
    }

    asm volatile("bar.sync %0, 64;" :: "r"(bar_id) : "memory");

    // ---- epilogue: normalize, emit fp16x2 y for the proj gemm ----
#pragma unroll
    for (int mt = 0; mt < 2; mt++) {
        int r0 = wm * 32 + mt * 16 + g, r1 = r0 + 8;
        float linv0 = 1.0f / l_s[r0];
        float linv1 = 1.0f / l_s[r1];
        uint32_t* y0 = y + ((size_t)b * SS + (size_t)qb * 128 + r0) * (DIM / 2)
                         + h * (HD / 2) + wn * 32;
        uint32_t* y1 = y + ((size_t)b * SS + (size_t)qb * 128 + r1) * (DIM / 2)
                         + h * (HD / 2) + wn * 32;
#pragma unroll
        for (int nt = 0; nt < 8; nt++) {
            y0[nt * 4 + t] = pack_h2(oacc[mt][nt][0] * linv0,
                                     oacc[mt][nt][1] * linv0);
            y1[nt * 4 + t] = pack_h2(oacc[mt][nt][2] * linv1,
                                     oacc[mt][nt][3] * linv1);
        }
    }
}

// =====================================================================
// host
// =====================================================================
extern "C" void kernel_launch(void* const* d_in, const int* in_sizes, int n_in,
                              void* d_out, int out_size)
{
    const float* x     = (const float*)d_in[0];
    const float* Wq    = (const float*)d_in[1];
    const float* Wk    = (const float*)d_in[2];
    const float* Wv    = (const float*)d_in[3];
    const float* Wproj = (const float*)d_in[4];
    const float* qg    = (const float*)d_in[5];
    float* out = (float*)d_out;

    float *qkv, *q, *k, *v;
    uint32_t *y, *xt, *wt, *wpt;
    cudaGetSymbolAddress((void**)&qkv, g_qkv);
    cudaGetSymbolAddress((void**)&q,   g_q);
    cudaGetSymbolAddress((void**)&k,   g_k);
    cudaGetSymbolAddress((void**)&v,   g_v);
    cudaGetSymbolAddress((void**)&y,   g_y);
    cudaGetSymbolAddress((void**)&xt,  g_xt);
    cudaGetSymbolAddress((void**)&wt,  g_wt);
    cudaGetSymbolAddress((void**)&wpt, g_wpt);

    cudaFuncSetAttribute(attn_mma,
                         cudaFuncAttributeMaxDynamicSharedMemorySize,
                         ATTN_WORDS * sizeof(uint32_t));
    cudaFuncSetAttribute(gemm_fp16,
                         cudaFuncAttributeMaxDynamicSharedMemorySize,
                         GEMM_SMEM_BYTES);

    // (0) RoPE tables
    rope_init<<<SS * 32 / 256, 256>>>();
    // (1) convert x -> fp16
    to_fp16<<<(MROWS * DIM / 4 + 255) / 256, 256>>>((const float4*)x, (uint2*)xt, MROWS * DIM / 4);
    // (2) convert Wq|Wk|Wv -> fp16 (one launch)
    to_fp16_w3<<<(QKVD * DIM / 4) / 256, 256>>>(
        (const float4*)Wq, (const float4*)Wk, (const float4*)Wv, (uint2*)wt);

    // (3) merged QKV projection, fp16 mma  <-- ncu lands here
    gemm_fp16<<<dim3(QKVD / 128, MROWS / 128), 256, GEMM_SMEM_BYTES>>>(
        xt, wt, qkv, DIM, QKVD, 0);

    // (4) RMS-norm + RoPE + gain + reshape (tf32 outputs for attn)
    norm_rope<<<dim3(BB * SS, NH + 2 * NKV), 128>>>(qkv, qg, q, k, v);

    // (5) flash attention -> g_y (fp16x2)
    attn_mma<<<dim3(SS / 128, NH, BB), 256,
               ATTN_WORDS * sizeof(uint32_t)>>>(q, k, v, y);

    // (6) convert Wproj -> fp16
    to_fp16<<<(DIM * DIM / 4 + 255) / 256, 256>>>((const float4*)Wproj, (uint2*)wpt, DIM * DIM / 4);

    // (7) output projection, fp16 mma
    gemm_fp16<<<dim3(DIM / 128, MROWS / 128), 256, GEMM_SMEM_BYTES>>>(
        y, wpt, out, DIM, DIM, 0);
}

// round 13
// speedup vs baseline: 1.7312x; 1.2134x over previous
#include <cuda_runtime.h>
#include <cuda_fp16.h>
#include <math.h>
#include <stdint.h>

#define DIM 2048
#define NH 16
#define NKV 4
#define HD 128
#define BB 4
#define SS 2048
#define KVD 512        // NKV*HD
#define QKVD 3072      // DIM + 2*KVD
#define MROWS (BB*SS)  // 8192
#define ATTN_SCALE 0.08838834764831845f  // 1/sqrt(128)

// ---------------- scratch (no allocations allowed) ----------------
__device__ float    g_qkv[(size_t)BB*SS*QKVD];     // fp32 gemm outputs
__device__ __half   g_qh[(size_t)BB*NH*SS*HD];     // fp16 q (scale folded)
__device__ __half   g_kh[(size_t)BB*NKV*SS*HD];    // fp16 k
__device__ __half   g_vh[(size_t)BB*NKV*SS*HD];    // fp16 v, s-paired layout
__device__ uint32_t g_y[(size_t)BB*SS*DIM/2];      // fp16x2 (attn out)
__device__ uint32_t g_xt[(size_t)MROWS*DIM/2];     // fp16x2 of x
__device__ uint32_t g_wt[(size_t)QKVD*DIM/2];      // fp16x2 Wq|Wk|Wv
__device__ uint32_t g_wpt[(size_t)DIM*DIM/2];      // fp16x2 Wproj
__device__ float    g_cosr[SS*32];
__device__ float    g_sinr[SS*32];

// =====================================================================
// helpers
// =====================================================================
__device__ __forceinline__ void mma_fp16(float* c, const uint32_t* a,
                                         uint32_t b0, uint32_t b1) {
    asm volatile(
        "mma.sync.aligned.m16n8k16.row.col.f32.f16.f16.f32 "
        "{%0,%1,%2,%3}, {%4,%5,%6,%7}, {%8,%9}, {%0,%1,%2,%3};"
        : "+f"(c[0]), "+f"(c[1]), "+f"(c[2]), "+f"(c[3])
        : "r"(a[0]), "r"(a[1]), "r"(a[2]), "r"(a[3]), "r"(b0), "r"(b1));
}

__device__ __forceinline__ void cpa16(uint32_t dst, const void* src) {
    asm volatile("cp.async.cg.shared.global [%0], [%1], 16;"
                 :: "r"(dst), "l"(src));
}

__device__ __forceinline__ uint32_t pack_h2(float x, float y) {
    __half2 h = __floats2half2_rn(x, y);
    return *(uint32_t*)&h;
}

// =====================================================================
// elementwise fp32 -> fp16x2 conversions
// =====================================================================
__global__ void to_fp16(const float4* __restrict__ src,
                        uint2* __restrict__ dst, int n4)
{
    int i = blockIdx.x * blockDim.x + threadIdx.x;
    if (i < n4) {
        float4 v = src[i];
        dst[i] = make_uint2(pack_h2(v.x, v.y), pack_h2(v.z, v.w));
    }
}

__global__ void to_fp16_w3(const float4* __restrict__ wq,
                           const float4* __restrict__ wk,
                           const float4* __restrict__ wv,
                           uint2* __restrict__ dst)
{
    int i = blockIdx.x * blockDim.x + threadIdx.x;
    const int nq = DIM * DIM / 4;
    const int nk = KVD * DIM / 4;
    float4 v;
    if (i < nq)            v = wq[i];
    else if (i < nq + nk)  v = wk[i - nq];
    else                   v = wv[i - nq - nk];
    dst[i] = make_uint2(pack_h2(v.x, v.y), pack_h2(v.z, v.w));
}

// =====================================================================
// fp16 warp-mma GEMM (R11 winner, unchanged)
// =====================================================================
#define SH 20
#define GSTG_W 5120
#define GEMM_SMEM_BYTES 61440

__global__ __launch_bounds__(256, 2)
void gemm_fp16(const uint32_t* __restrict__ A, const uint32_t* __restrict__ W,
               float* __restrict__ C, int K, int ldc, int coloff)
{
    extern __shared__ uint32_t sm[];
    const int KW   = K >> 1;
    const int tid  = threadIdx.x;
    const int lane = tid & 31;
    const int wid  = tid >> 5;
    const int wm   = wid & 3;
    const int wn   = wid >> 2;
    const int g    = lane >> 2;
    const int t    = lane & 3;
    const int m0   = blockIdx.y * 128;
    const int n0   = blockIdx.x * 128;
    const uint32_t smb = (uint32_t)__cvta_generic_to_shared(sm);

    float acc[2][8][4];
#pragma unroll
    for (int mt = 0; mt < 2; mt++)
#pragma unroll
        for (int nt = 0; nt < 8; nt++)
#pragma unroll
            for (int c = 0; c < 4; c++) acc[mt][nt][c] = 0.f;

    const int ntile = K >> 5;

    auto load_tile = [&](int it, int s) {
        const uint32_t base = (uint32_t)s * GSTG_W;
        const size_t kwb = (size_t)it * 16;
#pragma unroll
        for (int r = 0; r < 2; r++) {
            int id = tid + 256 * r;
            int row = id >> 2, c4 = (id & 3) * 4;
            cpa16(smb + (base + row * SH + c4) * 4,
                  A + (size_t)(m0 + row) * KW + kwb + c4);
            cpa16(smb + (base + 2560 + row * SH + c4) * 4,
                  W + (size_t)(n0 + row) * KW + kwb + c4);
        }
        asm volatile("cp.async.commit_group;");
    };

    load_tile(0, 0);
    load_tile(1, 1);

    int s = 0;
    for (int it = 0; it < ntile; it++) {
        if (it + 1 < ntile) {
            asm volatile("cp.async.wait_group 1;");
        } else {
            asm volatile("cp.async.wait_group 0;");
        }
        __syncthreads();

        if (it + 2 < ntile) {
            int s2 = s + 2; if (s2 >= 3) s2 -= 3;
            load_tile(it + 2, s2);
        }

        const uint32_t* As = sm + (uint32_t)s * GSTG_W;
        const uint32_t* Bs = As + 2560;
#pragma unroll
        for (int h = 0; h < 2; h++) {
            const int base = h * 8;
            uint32_t a[2][4];
#pragma unroll
            for (int mt = 0; mt < 2; mt++) {
                int rb = wm * 32 + mt * 16;
                a[mt][0] = As[(rb + g    ) * SH + base + t    ];
                a[mt][1] = As[(rb + g + 8) * SH + base + t    ];
                a[mt][2] = As[(rb + g    ) * SH + base + t + 4];
                a[mt][3] = As[(rb + g + 8) * SH + base + t + 4];
            }
#pragma unroll
            for (int nt = 0; nt < 8; nt++) {
                int nb = wn * 64 + nt * 8 + g;
                uint32_t b0 = Bs[nb * SH + base + t    ];
                uint32_t b1 = Bs[nb * SH + base + t + 4];
                mma_fp16(acc[0][nt], a[0], b0, b1);
                mma_fp16(acc[1][nt], a[1], b0, b1);
            }
        }
        if (++s >= 3) s = 0;
    }

#pragma unroll
    for (int mt = 0; mt < 2; mt++) {
        int row = m0 + wm * 32 + mt * 16 + g;
#pragma unroll
        for (int nt = 0; nt < 8; nt++) {
            int col = coloff + n0 + wn * 64 + nt * 8 + 2 * t;
            float2 v01 = make_float2(acc[mt][nt][0], acc[mt][nt][1]);
            float2 v23 = make_float2(acc[mt][nt][2], acc[mt][nt][3]);
            *(float2*)(C + (size_t)row * ldc + col)       = v01;
            *(float2*)(C + (size_t)(row + 8) * ldc + col) = v23;
        }
    }
}

// =====================================================================
// RoPE table init
// =====================================================================
__global__ void rope_init()
{
    int i = blockIdx.x * blockDim.x + threadIdx.x;
    int s = i >> 5, f = i & 31;
    double inv = pow(10000.0, -(double)f / 32.0);
    double ang = (double)s * inv;
    double sd, cd;
    sincos(ang, &sd, &cd);
    g_cosr[i] = (float)cd;
    g_sinr[i] = (float)sd;
}

// =====================================================================
// RMS-norm + RoPE + gain + reshape; q/k fp16 natural, v fp16 s-paired:
// half index = (s & ~1)*HD + 2*d + (s & 1)   (word m*HD+d = V[2m],V[2m+1])
// =====================================================================
__global__ void norm_rope(const float* __restrict__ qkv,
                          const float* __restrict__ q_gain,
                          __half* __restrict__ q, __half* __restrict__ k,
                          __half* __restrict__ v)
{
    const int bs   = blockIdx.x;
    const int head = blockIdx.y;
    const int b = bs / SS, s = bs % SS;
    const int d = threadIdx.x;

    if (head >= NH + NKV) {
        int kv = head - NH - NKV;
        float val = qkv[(size_t)bs * QKVD + DIM + KVD + kv * HD + d];
        size_t base = (size_t)(b * NKV + kv) * SS * HD;
        v[base + (size_t)(s & ~1) * HD + 2 * d + (s & 1)] = __float2half_rn(val);
        return;
    }
    const bool isq = (head < NH);
    const float* row = qkv + (size_t)bs * QKVD +
                       (isq ? head * HD : DIM + (head - NH) * HD);
    float val = row[d];

    __shared__ float red[4];
    __shared__ float xs[HD];
    float sq = val * val;
#pragma unroll
    for (int o = 16; o > 0; o >>= 1) sq += __shfl_xor_sync(0xffffffffu, sq, o);
    if ((d & 31) == 0) red[d >> 5] = sq;
    __syncthreads();
    float ms = (red[0] + red[1] + red[2] + red[3]) * (1.0f / HD);
    float xn = val * rsqrtf(ms + 1.1920929e-07f);
    xs[d] = xn;
    __syncthreads();

    float outv;
    if (d < 64) {
        int f = d & 31;
        float c  = g_cosr[s * 32 + f];
        float sn = g_sinr[s * 32 + f];
        float x1 = xs[f], x2 = xs[f + 32];
        outv = (d < 32) ? (x1 * c + x2 * sn) : (-x1 * sn + x2 * c);
    } else {
        outv = xn;
    }

    if (isq) {
        outv *= q_gain[head] * ATTN_SCALE;
        q[((size_t)(b * NH + head) * SS + s) * HD + d] = __float2half_rn(outv);
    } else {
        int kv = head - NH;
        k[((size_t)(b * NKV + kv) * SS + s) * HD + d] = __float2half_rn(outv);
    }
}

// =====================================================================
// fp16 flash attention, Q tile 128, kv tile 64, 2 CTAs/SM.
// Word strides: Q/K 68 (==4 mod 32), P 36 (==4), V2 136 (==8).
// V is s-paired: word (m, d) = (V[2m][d], V[2m+1][d]).
// =====================================================================
#define QS_OFF   0            // 128 x 68
#define KS_OFF   8704         // 64 x 68
#define VS_OFF0  13056        // 32 x 136
#define VS_OFF1  17408
#define PS_OFF   21760        // 128 x 36
#define PMAX_OFF 26368        // [2][128]
#define PSUM_OFF 26624        // [2][128]
#define MS_OFF   26880        // [128]
#define LS_OFF   27008        // [128]
#define ATTN_WORDS 27136      // 108,544 bytes

__global__ __launch_bounds__(256, 2)
void attn_mma(const __half* __restrict__ q, const __half* __restrict__ k,
              const __half* __restrict__ v, uint32_t* __restrict__ y)
{
    extern __shared__ uint32_t sm[];
    const int qb = (int)gridDim.x - 1 - (int)blockIdx.x;
    const int h = blockIdx.y, b = blockIdx.z;
    const int kvh = h >> 2;
    const int tid = threadIdx.x;
    const int lane = tid & 31, wid = tid >> 5;
    const int g = lane >> 2, t = lane & 3;
    const int wm = wid & 3, wn = wid >> 2;
    const int bar_id = 1 + wm;

    const __half* qbase = q + ((size_t)(b * NH + h) * SS + (size_t)qb * 128) * HD;
    const __half* kbase = k + ((size_t)(b * NKV + kvh) * SS) * HD;
    const __half* vbase = v + ((size_t)(b * NKV + kvh) * SS) * HD;  // paired

    const uint32_t smb = (uint32_t)__cvta_generic_to_shared(sm);

    float* m_s  = (float*)(sm + MS_OFF);
    float* l_s  = (float*)(sm + LS_OFF);
    float* pmax = (float*)(sm + PMAX_OFF);
    float* psum = (float*)(sm + PSUM_OFF);

    // Q: 128 rows x 16 chunks(8h) ; K: 64 x 16 ; V2: 32 rows x 32 chunks
#pragma unroll
    for (int i = 0; i < 8; i++) {
        int id = tid + 256 * i;
        int row = id >> 4, c = id & 15;
        cpa16(smb + (QS_OFF + row * 68 + c * 4) * 4, qbase + (size_t)row * HD + c * 8);
    }
#pragma unroll
    for (int i = 0; i < 4; i++) {
        int id = tid + 256 * i;
        int row = id >> 4, c = id & 15;
        cpa16(smb + (KS_OFF + row * 68 + c * 4) * 4, kbase + (size_t)row * HD + c * 8);
    }
#pragma unroll
    for (int i = 0; i < 4; i++) {
        int id = tid + 256 * i;
        int row = id >> 5, c = id & 31;
        cpa16(smb + (VS_OFF0 + row * 136 + c * 4) * 4, vbase + (size_t)row * 256 + c * 8);
    }
    asm volatile("cp.async.commit_group;");

    if (tid < 128) { m_s[tid] = -1e30f; l_s[tid] = 0.f; }

    float oacc[2][8][4];
#pragma unroll
    for (int mt = 0; mt < 2; mt++)
#pragma unroll
        for (int nt = 0; nt < 8; nt++)
#pragma unroll
            for (int c = 0; c < 4; c++) oacc[mt][nt][c] = 0.f;

    const int nkv = 2 * qb + 2;

    asm volatile("cp.async.wait_group 0;");
    __syncthreads();

    for (int kvt = 0; kvt < nkv; kvt++) {
        const int cur = kvt & 1;

        // ---- S = Q K^T (fp16, 8 k16 steps over HD=128) ----
        float sacc[2][4][4];
#pragma unroll
        for (int mt = 0; mt < 2; mt++)
#pragma unroll
            for (int nt = 0; nt < 4; nt++)
#pragma unroll
                for (int c = 0; c < 4; c++) sacc[mt][nt][c] = 0.f;

        const uint32_t* Qb = sm + QS_OFF + (wm * 32) * 68;
        const uint32_t* Kb = sm + KS_OFF + (wn * 32) * 68;
#pragma unroll
        for (int ks = 0; ks < 8; ks++) {
            const int kb = ks * 8;
            uint32_t a[2][4];
#pragma unroll
            for (int mt = 0; mt < 2; mt++) {
                const uint32_t* Qr = Qb + mt * 16 * 68;
                a[mt][0] = Qr[g * 68 + kb + t];
                a[mt][1] = Qr[(g + 8) * 68 + kb + t];
                a[mt][2] = Qr[g * 68 + kb + t + 4];
                a[mt][3] = Qr[(g + 8) * 68 + kb + t + 4];
            }
#pragma unroll
            for (int nt = 0; nt < 4; nt++) {
                uint32_t b0 = Kb[(nt * 8 + g) * 68 + kb + t];
                uint32_t b1 = Kb[(nt * 8 + g) * 68 + kb + t + 4];
                mma_fp16(sacc[0][nt], a[0], b0, b1);
                mma_fp16(sacc[1][nt], a[1], b0, b1);
            }
        }

        if (kvt >= 2 * qb) {
            const int off = (kvt - 2 * qb) * 64;
#pragma unroll
            for (int mt = 0; mt < 2; mt++) {
                int r0 = wm * 32 + mt * 16 + g, r1 = r0 + 8;
#pragma unroll
                for (int nt = 0; nt < 4; nt++) {
                    int c = wn * 32 + nt * 8 + 2 * t + off;
                    if (c     > r0) sacc[mt][nt][0] = -1e30f;
                    if (c + 1 > r0) sacc[mt][nt][1] = -1e30f;
                    if (c     > r1) sacc[mt][nt][2] = -1e30f;
                    if (c + 1 > r1) sacc[mt][nt][3] = -1e30f;
                }
            }
        }

#pragma unroll
        for (int mt = 0; mt < 2; mt++) {
            float rm0 = -1e30f, rm1 = -1e30f;
#pragma unroll
            for (int nt = 0; nt < 4; nt++) {
                rm0 = fmaxf(rm0, fmaxf(sacc[mt][nt][0], sacc[mt][nt][1]));
                rm1 = fmaxf(rm1, fmaxf(sacc[mt][nt][2], sacc[mt][nt][3]));
            }
            rm0 = fmaxf(rm0, __shfl_xor_sync(0xffffffffu, rm0, 1));
            rm0 = fmaxf(rm0, __shfl_xor_sync(0xffffffffu, rm0, 2));
            rm1 = fmaxf(rm1, __shfl_xor_sync(0xffffffffu, rm1, 1));
            rm1 = fmaxf(rm1, __shfl_xor_sync(0xffffffffu, rm1, 2));
            if (t == 0) {
                pmax[wn * 128 + wm * 32 + mt * 16 + g]     = rm0;
                pmax[wn * 128 + wm * 32 + mt * 16 + g + 8] = rm1;
            }
        }
        asm volatile("bar.sync %0, 64;" :: "r"(bar_id) : "memory");

        // ---- softmax; P stored as fp16 pairs (one word per (row, kword)) ----
        float alpha[2][2], mnew[2][2];
#pragma unroll
        for (int mt = 0; mt < 2; mt++) {
            int r0 = wm * 32 + mt * 16 + g, r1 = r0 + 8;
            float mo0 = m_s[r0], mo1 = m_s[r1];
            float mn0 = fmaxf(mo0, fmaxf(pmax[r0], pmax[128 + r0]));
            float mn1 = fmaxf(mo1, fmaxf(pmax[r1], pmax[128 + r1]));
            alpha[mt][0] = __expf(mo0 - mn0);
            alpha[mt][1] = __expf(mo1 - mn1);
            mnew[mt][0] = mn0; mnew[mt][1] = mn1;
            float rs0 = 0.f, rs1 = 0.f;
#pragma unroll
            for (int nt = 0; nt < 4; nt++) {
                float p00 = __expf(sacc[mt][nt][0] - mn0);
                float p01 = __expf(sacc[mt][nt][1] - mn0);
                float p10 = __expf(sacc[mt][nt][2] - mn1);
                float p11 = __expf(sacc[mt][nt][3] - mn1);
                rs0 += p00 + p01;
                rs1 += p10 + p11;
                int w = wn * 16 + nt * 4 + t;            // k-word index
                sm[PS_OFF + r0 * 36 + w] = pack_h2(p00, p01);
                sm[PS_OFF + r1 * 36 + w] = pack_h2(p10, p11);
            }
            rs0 += __shfl_xor_sync(0xffffffffu, rs0, 1);
            rs0 += __shfl_xor_sync(0xffffffffu, rs0, 2);
            rs1 += __shfl_xor_sync(0xffffffffu, rs1, 1);
            rs1 += __shfl_xor_sync(0xffffffffu, rs1, 2);
            if (t == 0) {
                psum[wn * 128 + r0] = rs0;
                psum[wn * 128 + r1] = rs1;
            }
        }
#pragma unroll
        for (int mt = 0; mt < 2; mt++)
#pragma unroll
            for (int nt = 0; nt < 8; nt++) {
                oacc[mt][nt][0] *= alpha[mt][0];
                oacc[mt][nt][1] *= alpha[mt][0];
                oacc[mt][nt][2] *= alpha[mt][1];
                oacc[mt][nt][3] *= alpha[mt][1];
            }
        asm volatile("bar.sync %0, 64;" :: "r"(bar_id) : "memory");
        if (wn == 0 && t == 0) {
#pragma unroll
            for (int mt = 0; mt < 2; mt++) {
                int r0 = wm * 32 + mt * 16 + g, r1 = r0 + 8;
                l_s[r0] = l_s[r0] * alpha[mt][0] + psum[r0] + psum[128 + r0];
                l_s[r1] = l_s[r1] * alpha[mt][1] + psum[r1] + psum[128 + r1];
                m_s[r0] = mnew[mt][0];
                m_s[r1] = mnew[mt][1];
            }
        }

        __syncthreads();
        if (kvt + 1 < nkv) {
            const __half* kn = kbase + (size_t)(kvt + 1) * 64 * HD;
            const __half* vn = vbase + (size_t)(kvt + 1) * 64 * HD;  // 32 rows x 256 h
            const uint32_t vo = cur ? VS_OFF0 : VS_OFF1;
#pragma unroll
            for (int i = 0; i < 4; i++) {
                int id = tid + 256 * i;
                int row = id >> 4, c = id & 15;
                cpa16(smb + (KS_OFF + row * 68 + c * 4) * 4, kn + (size_t)row * HD + c * 8);
            }
#pragma unroll
            for (int i = 0; i < 4; i++) {
                int id = tid + 256 * i;
                int row = id >> 5, c = id & 31;
                cpa16(smb + (vo + row * 136 + c * 4) * 4, vn + (size_t)row * 256 + c * 8);
            }
            asm volatile("cp.async.commit_group;");
        }

        // ---- O += P V (fp16, 4 k16 steps over 64 kv rows) ----
        const uint32_t* Pb = sm + PS_OFF + (wm * 32) * 36;
        const uint32_t* Vb = sm + (cur ? VS_OFF1 : VS_OFF0) + wn * 64;
#pragma unroll
        for (int ks = 0; ks < 4; ks++) {
            const int kb = ks * 8;
            uint32_t a[2][4];
#pragma unroll
            for (int mt = 0; mt < 2; mt++) {
                const uint32_t* Pr = Pb + mt * 16 * 36;
                a[mt][0] = Pr[g * 36 + kb + t];
                a[mt][1] = Pr[(g + 8) * 36 + kb + t];
                a[mt][2] = Pr[g * 36 + kb + t + 4];
                a[mt][3] = Pr[(g + 8) * 36 + kb + t + 4];
            }
#pragma unroll
            for (int nt = 0; nt < 8; nt++) {
                uint32_t b0 = Vb[(kb + t) * 136 + nt * 8 + g];
                uint32_t b1 = Vb[(kb + t + 4) * 136 + nt * 8 + g];
                mma_fp16(oacc[0][nt], a[0], b0, b1);
                mma_fp16(oacc[1][nt], a[1], b0, b1);
            }
        }

        if (kvt + 1 < nkv) {
            asm volatile("cp.async.wait_group 0;");
            __syncthreads();
        }
    }

    asm volatile("bar.sync %0, 64;" :: "r"(bar_id) : "memory");

    // ---- epilogue: normalize, emit fp16x2 y ----
#pragma unroll
    for (int mt = 0; mt < 2; mt++) {
        int r0 = wm * 32 + mt * 16 + g, r1 = r0 + 8;
        float linv0 = 1.0f / l_s[r0];
        float linv1 = 1.0f / l_s[r1];
        uint32_t* y0 = y + ((size_t)b * SS + (size_t)qb * 128 + r0) * (DIM / 2)
                         + h * (HD / 2) + wn * 32;
        uint32_t* y1 = y + ((size_t)b * SS + (size_t)qb * 128 + r1) * (DIM / 2)
                         + h * (HD / 2) + wn * 32;
#pragma unroll
        for (int nt = 0; nt < 8; nt++) {
            y0[nt * 4 + t] = pack_h2(oacc[mt][nt][0] * linv0,
                                     oacc[mt][nt][1] * linv0);
            y1[nt * 4 + t] = pack_h2(oacc[mt][nt][2] * linv1,
                                     oacc[mt][nt][3] * linv1);
        }
    }
}

// =====================================================================
// host
// =====================================================================
extern "C" void kernel_launch(void* const* d_in, const int* in_sizes, int n_in,
                              void* d_out, int out_size)
{
    const float* x     = (const float*)d_in[0];
    const float* Wq    = (const float*)d_in[1];
    const float* Wk    = (const float*)d_in[2];
    const float* Wv    = (const float*)d_in[3];
    const float* Wproj = (const float*)d_in[4];
    const float* qg    = (const float*)d_in[5];
    float* out = (float*)d_out;

    float* qkv;
    __half *qh, *kh, *vh;
    uint32_t *y, *xt, *wt, *wpt;
    cudaGetSymbolAddress((void**)&qkv, g_qkv);
    cudaGetSymbolAddress((void**)&qh,  g_qh);
    cudaGetSymbolAddress((void**)&kh,  g_kh);
    cudaGetSymbolAddress((void**)&vh,  g_vh);
    cudaGetSymbolAddress((void**)&y,   g_y);
    cudaGetSymbolAddress((void**)&xt,  g_xt);
    cudaGetSymbolAddress((void**)&wt,  g_wt);
    cudaGetSymbolAddress((void**)&wpt, g_wpt);

    cudaFuncSetAttribute(attn_mma,
                         cudaFuncAttributeMaxDynamicSharedMemorySize,
                         ATTN_WORDS * sizeof(uint32_t));
    cudaFuncSetAttribute(gemm_fp16,
                         cudaFuncAttributeMaxDynamicSharedMemorySize,
                         GEMM_SMEM_BYTES);

    // (0) RoPE tables
    rope_init<<<SS * 32 / 256, 256>>>();
    // (1) convert x -> fp16
    to_fp16<<<(MROWS * DIM / 4 + 255) / 256, 256>>>((const float4*)x, (uint2*)xt, MROWS * DIM / 4);
    // (2) convert Wq|Wk|Wv -> fp16
    to_fp16_w3<<<(QKVD * DIM / 4) / 256, 256>>>(
        (const float4*)Wq, (const float4*)Wk, (const float4*)Wv, (uint2*)wt);

    // (3) merged QKV projection  <-- ncu lands here
    gemm_fp16<<<dim3(QKVD / 128, MROWS / 128), 256, GEMM_SMEM_BYTES>>>(
        xt, wt, qkv, DIM, QKVD, 0);

    // (4) RMS-norm + RoPE + gain + reshape (fp16 outputs)
    norm_rope<<<dim3(BB * SS, NH + 2 * NKV), 128>>>(qkv, qg, qh, kh, vh);

    // (5) fp16 flash attention -> g_y
    attn_mma<<<dim3(SS / 128, NH, BB), 256,
               ATTN_WORDS * sizeof(uint32_t)>>>(qh, kh, vh, y);

    // (6) convert Wproj -> fp16
    to_fp16<<<(DIM * DIM / 4 + 255) / 256, 256>>>((const float4*)Wproj, (uint2*)wpt, DIM * DIM / 4);

    // (7) output projection
    gemm_fp16<<<dim3(DIM / 128, MROWS / 128), 256, GEMM_SMEM_BYTES>>>(
        y, wpt, out, DIM, DIM, 0);
}

// round 14
// speedup vs baseline: 1.8665x; 1.0782x over previous
#include <cuda_runtime.h>
#include <cuda_fp16.h>
#include <math.h>
#include <stdint.h>

#define DIM 2048
#define NH 16
#define NKV 4
#define HD 128
#define BB 4
#define SS 2048
#define KVD 512        // NKV*HD
#define QKVD 3072      // DIM + 2*KVD
#define MROWS (BB*SS)  // 8192
#define ATTN_SCALE 0.08838834764831845f  // 1/sqrt(128)

// ---------------- scratch (no allocations allowed) ----------------
__device__ __half   g_qh[(size_t)BB*NH*SS*HD];     // fp16 q (scale folded)
__device__ __half   g_kh[(size_t)BB*NKV*SS*HD];    // fp16 k
__device__ __half   g_vh[(size_t)BB*NKV*SS*HD];    // fp16 v, s-paired layout
__device__ uint32_t g_y[(size_t)BB*SS*DIM/2];      // fp16x2 (attn out)
__device__ uint32_t g_xt[(size_t)MROWS*DIM/2];     // fp16x2 of x
__device__ uint32_t g_wt[(size_t)QKVD*DIM/2];      // fp16x2 Wq|Wk|Wv
__device__ uint32_t g_wpt[(size_t)DIM*DIM/2];      // fp16x2 Wproj
__device__ float    g_cosr[SS*32];
__device__ float    g_sinr[SS*32];

// =====================================================================
// helpers
// =====================================================================
__device__ __forceinline__ void mma_fp16(float* c, const uint32_t* a,
                                         uint32_t b0, uint32_t b1) {
    asm volatile(
        "mma.sync.aligned.m16n8k16.row.col.f32.f16.f16.f32 "
        "{%0,%1,%2,%3}, {%4,%5,%6,%7}, {%8,%9}, {%0,%1,%2,%3};"
        : "+f"(c[0]), "+f"(c[1]), "+f"(c[2]), "+f"(c[3])
        : "r"(a[0]), "r"(a[1]), "r"(a[2]), "r"(a[3]), "r"(b0), "r"(b1));
}

__device__ __forceinline__ void cpa16(uint32_t dst, const void* src) {
    asm volatile("cp.async.cg.shared.global [%0], [%1], 16;"
                 :: "r"(dst), "l"(src));
}

__device__ __forceinline__ uint32_t pack_h2(float x, float y) {
    __half2 h = __floats2half2_rn(x, y);
    return *(uint32_t*)&h;
}

// =====================================================================
// elementwise fp32 -> fp16x2 conversions
// =====================================================================
__global__ void to_fp16(const float4* __restrict__ src,
                        uint2* __restrict__ dst, int n4)
{
    int i = blockIdx.x * blockDim.x + threadIdx.x;
    if (i < n4) {
        float4 v = src[i];
        dst[i] = make_uint2(pack_h2(v.x, v.y), pack_h2(v.z, v.w));
    }
}

__global__ void to_fp16_w3(const float4* __restrict__ wq,
                           const float4* __restrict__ wk,
                           const float4* __restrict__ wv,
                           uint2* __restrict__ dst)
{
    int i = blockIdx.x * blockDim.x + threadIdx.x;
    const int nq = DIM * DIM / 4;
    const int nk = KVD * DIM / 4;
    float4 v;
    if (i < nq)            v = wq[i];
    else if (i < nq + nk)  v = wk[i - nq];
    else                   v = wv[i - nq - nk];
    dst[i] = make_uint2(pack_h2(v.x, v.y), pack_h2(v.z, v.w));
}

// =====================================================================
// RoPE table init
// =====================================================================
__global__ void rope_init()
{
    int i = blockIdx.x * blockDim.x + threadIdx.x;
    int s = i >> 5, f = i & 31;
    double inv = pow(10000.0, -(double)f / 32.0);
    double ang = (double)s * inv;
    double sd, cd;
    sincos(ang, &sd, &cd);
    g_cosr[i] = (float)cd;
    g_sinr[i] = (float)sd;
}

// =====================================================================
// fp16 warp-mma GEMM, 128x128x32 tiles, 3-stage cp.async (R11/R12 core).
// FUSE=0: plain fp32 C output (output projection).
// FUSE=1: QKV path — col-tile == one head; epilogue does RMS-norm +
//         RoPE + gain and writes fp16 q/k/v directly (v s-paired).
// =====================================================================
#define SH 20
#define GSTG_W 5120
#define GEMM_SMEM_BYTES 61440

template<bool FUSE>
__global__ __launch_bounds__(256, 2)
void gemm_fp16_t(const uint32_t* __restrict__ A, const uint32_t* __restrict__ W,
                 float* __restrict__ C, const float* __restrict__ qg,
                 int K, int ldc, int coloff)
{
    extern __shared__ uint32_t sm[];
    const int KW   = K >> 1;
    const int tid  = threadIdx.x;
    const int lane = tid & 31;
    const int wid  = tid >> 5;
    const int wm   = wid & 3;
    const int wn   = wid >> 2;
    const int g    = lane >> 2;
    const int t    = lane & 3;
    const int m0   = blockIdx.y * 128;
    const int n0   = blockIdx.x * 128;
    const uint32_t smb = (uint32_t)__cvta_generic_to_shared(sm);

    float acc[2][8][4];
#pragma unroll
    for (int mt = 0; mt < 2; mt++)
#pragma unroll
        for (int nt = 0; nt < 8; nt++)
#pragma unroll
            for (int c = 0; c < 4; c++) acc[mt][nt][c] = 0.f;

    const int ntile = K >> 5;

    auto load_tile = [&](int it, int s) {
        const uint32_t base = (uint32_t)s * GSTG_W;
        const size_t kwb = (size_t)it * 16;
#pragma unroll
        for (int r = 0; r < 2; r++) {
            int id = tid + 256 * r;
            int row = id >> 2, c4 = (id & 3) * 4;
            cpa16(smb + (base + row * SH + c4) * 4,
                  A + (size_t)(m0 + row) * KW + kwb + c4);
            cpa16(smb + (base + 2560 + row * SH + c4) * 4,
                  W + (size_t)(n0 + row) * KW + kwb + c4);
        }
        asm volatile("cp.async.commit_group;");
    };

    load_tile(0, 0);
    load_tile(1, 1);

    int s = 0;
    for (int it = 0; it < ntile; it++) {
        if (it + 1 < ntile) {
            asm volatile("cp.async.wait_group 1;");
        } else {
            asm volatile("cp.async.wait_group 0;");
        }
        __syncthreads();

        if (it + 2 < ntile) {
            int s2 = s + 2; if (s2 >= 3) s2 -= 3;
            load_tile(it + 2, s2);
        }

        const uint32_t* As = sm + (uint32_t)s * GSTG_W;
        const uint32_t* Bs = As + 2560;
#pragma unroll
        for (int h = 0; h < 2; h++) {
            const int base = h * 8;
            uint32_t a[2][4];
#pragma unroll
            for (int mt = 0; mt < 2; mt++) {
                int rb = wm * 32 + mt * 16;
                a[mt][0] = As[(rb + g    ) * SH + base + t    ];
                a[mt][1] = As[(rb + g + 8) * SH + base + t    ];
                a[mt][2] = As[(rb + g    ) * SH + base + t + 4];
                a[mt][3] = As[(rb + g + 8) * SH + base + t + 4];
            }
#pragma unroll
            for (int nt = 0; nt < 8; nt++) {
                int nb = wn * 64 + nt * 8 + g;
                uint32_t b0 = Bs[nb * SH + base + t    ];
                uint32_t b1 = Bs[nb * SH + base + t + 4];
                mma_fp16(acc[0][nt], a[0], b0, b1);
                mma_fp16(acc[1][nt], a[1], b0, b1);
            }
        }
        if (++s >= 3) s = 0;
    }

    if (!FUSE) {
        // plain fp32 epilogue (output projection)
#pragma unroll
        for (int mt = 0; mt < 2; mt++) {
            int row = m0 + wm * 32 + mt * 16 + g;
#pragma unroll
            for (int nt = 0; nt < 8; nt++) {
                int col = coloff + n0 + wn * 64 + nt * 8 + 2 * t;
                float2 v01 = make_float2(acc[mt][nt][0], acc[mt][nt][1]);
                float2 v23 = make_float2(acc[mt][nt][2], acc[mt][nt][3]);
                *(float2*)(C + (size_t)row * ldc + col)       = v01;
                *(float2*)(C + (size_t)(row + 8) * ldc + col) = v23;
            }
        }
        return;
    }

    // ================= FUSED norm+rope epilogue (QKV) =================
    const int head  = n0 >> 7;          // 0..15 q | 16..19 k | 20..23 v
    const int bq    = m0 >> 11;         // batch (tile never straddles)
    const int sbase = m0 & (SS - 1);
    float* red = (float*)sm;            // [2][128] row partial sums

    // local sum of squares per (mt, half-row)
    float ss[2][2];
#pragma unroll
    for (int mt = 0; mt < 2; mt++) { ss[mt][0] = 0.f; ss[mt][1] = 0.f; }
#pragma unroll
    for (int mt = 0; mt < 2; mt++)
#pragma unroll
        for (int nt = 0; nt < 8; nt++) {
            ss[mt][0] += acc[mt][nt][0] * acc[mt][nt][0]
                       + acc[mt][nt][1] * acc[mt][nt][1];
            ss[mt][1] += acc[mt][nt][2] * acc[mt][nt][2]
                       + acc[mt][nt][3] * acc[mt][nt][3];
        }
#pragma unroll
    for (int mt = 0; mt < 2; mt++)
#pragma unroll
        for (int hf = 0; hf < 2; hf++) {
            ss[mt][hf] += __shfl_xor_sync(0xffffffffu, ss[mt][hf], 1);
            ss[mt][hf] += __shfl_xor_sync(0xffffffffu, ss[mt][hf], 2);
        }

    __syncthreads();     // all smem tile reads done before reuse
    if (t == 0) {
#pragma unroll
        for (int mt = 0; mt < 2; mt++) {
            red[wn * 128 + wm * 32 + mt * 16 + g]     = ss[mt][0];
            red[wn * 128 + wm * 32 + mt * 16 + g + 8] = ss[mt][1];
        }
    }
    __syncthreads();

    const float gscale = (head < 16) ? qg[head] * ATTN_SCALE : 1.0f;

#pragma unroll
    for (int mt = 0; mt < 2; mt++) {
#pragma unroll
        for (int hf = 0; hf < 2; hf++) {
            const int r  = wm * 32 + mt * 16 + g + hf * 8;
            const int sg = sbase + r;

            float vv[8][2];
            if (head < 20) {
                float sum = red[r] + red[128 + r];
                float rinv = rsqrtf(sum * (1.0f / HD) + 1.1920929e-07f) * gscale;
#pragma unroll
                for (int nt = 0; nt < 8; nt++) {
                    vv[nt][0] = acc[mt][nt][hf * 2 + 0] * rinv;
                    vv[nt][1] = acc[mt][nt][hf * 2 + 1] * rinv;
                }
                if (wn == 0) {   // cols 0..63 -> rope rotate (pairs nt, nt+4)
#pragma unroll
                    for (int nt = 0; nt < 4; nt++)
#pragma unroll
                        for (int j = 0; j < 2; j++) {
                            int f = nt * 8 + 2 * t + j;
                            float c  = g_cosr[sg * 32 + f];
                            float sn = g_sinr[sg * 32 + f];
                            float x1 = vv[nt][j], x2 = vv[nt + 4][j];
                            vv[nt][j]     =  x1 * c + x2 * sn;
                            vv[nt + 4][j] = -x1 * sn + x2 * c;
                        }
                }
                __half* dst = (head < 16)
                    ? g_qh + ((size_t)(bq * NH + head) * SS + sg) * HD
                    : g_kh + ((size_t)(bq * NKV + head - 16) * SS + sg) * HD;
                dst += wn * 64;
#pragma unroll
                for (int nt = 0; nt < 8; nt++)
                    *(uint32_t*)(dst + nt * 8 + 2 * t) = pack_h2(vv[nt][0], vv[nt][1]);
            } else {
                // V: plain convert, s-paired layout
                __half* dst = g_vh + (size_t)(bq * NKV + head - 20) * SS * HD
                            + (size_t)(sg & ~1) * HD + (sg & 1) + (size_t)wn * 128;
#pragma unroll
                for (int nt = 0; nt < 8; nt++) {
                    int c0 = nt * 8 + 2 * t;
                    dst[2 * c0]     = __float2half_rn(acc[mt][nt][hf * 2 + 0]);
                    dst[2 * c0 + 2] = __float2half_rn(acc[mt][nt][hf * 2 + 1]);
                }
            }
        }
    }
}

// =====================================================================
// fp16 flash attention (R12 winner, unchanged)
// =====================================================================
#define QS_OFF   0            // 128 x 68
#define KS_OFF   8704         // 64 x 68
#define VS_OFF0  13056        // 32 x 136
#define VS_OFF1  17408
#define PS_OFF   21760        // 128 x 36
#define PMAX_OFF 26368        // [2][128]
#define PSUM_OFF 26624        // [2][128]
#define MS_OFF   26880        // [128]
#define LS_OFF   27008        // [128]
#define ATTN_WORDS 27136      // 108,544 bytes

__global__ __launch_bounds__(256, 2)
void attn_mma(const __half* __restrict__ q, const __half* __restrict__ k,
              const __half* __restrict__ v, uint32_t* __restrict__ y)
{
    extern __shared__ uint32_t sm[];
    const int qb = (int)gridDim.x - 1 - (int)blockIdx.x;
    const int h = blockIdx.y, b = blockIdx.z;
    const int kvh = h >> 2;
    const int tid = threadIdx.x;
    const int lane = tid & 31, wid = tid >> 5;
    const int g = lane >> 2, t = lane & 3;
    const int wm = wid & 3, wn = wid >> 2;
    const int bar_id = 1 + wm;

    const __half* qbase = q + ((size_t)(b * NH + h) * SS + (size_t)qb * 128) * HD;
    const __half* kbase = k + ((size_t)(b * NKV + kvh) * SS) * HD;
    const __half* vbase = v + ((size_t)(b * NKV + kvh) * SS) * HD;  // paired

    const uint32_t smb = (uint32_t)__cvta_generic_to_shared(sm);

    float* m_s  = (float*)(sm + MS_OFF);
    float* l_s  = (float*)(sm + LS_OFF);
    float* pmax = (float*)(sm + PMAX_OFF);
    float* psum = (float*)(sm + PSUM_OFF);

#pragma unroll
    for (int i = 0; i < 8; i++) {
        int id = tid + 256 * i;
        int row = id >> 4, c = id & 15;
        cpa16(smb + (QS_OFF + row * 68 + c * 4) * 4, qbase + (size_t)row * HD + c * 8);
    }
#pragma unroll
    for (int i = 0; i < 4; i++) {
        int id = tid + 256 * i;
        int row = id >> 4, c = id & 15;
        cpa16(smb + (KS_OFF + row * 68 + c * 4) * 4, kbase + (size_t)row * HD + c * 8);
    }
#pragma unroll
    for (int i = 0; i < 4; i++) {
        int id = tid + 256 * i;
        int row = id >> 5, c = id & 31;
        cpa16(smb + (VS_OFF0 + row * 136 + c * 4) * 4, vbase + (size_t)row * 256 + c * 8);
    }
    asm volatile("cp.async.commit_group;");

    if (tid < 128) { m_s[tid] = -1e30f; l_s[tid] = 0.f; }

    float oacc[2][8][4];
#pragma unroll
    for (int mt = 0; mt < 2; mt++)
#pragma unroll
        for (int nt = 0; nt < 8; nt++)
#pragma unroll
            for (int c = 0; c < 4; c++) oacc[mt][nt][c] = 0.f;

    const int nkv = 2 * qb + 2;

    asm volatile("cp.async.wait_group 0;");
    __syncthreads();

    for (int kvt = 0; kvt < nkv; kvt++) {
        const int cur = kvt & 1;

        float sacc[2][4][4];
#pragma unroll
        for (int mt = 0; mt < 2; mt++)
#pragma unroll
            for (int nt = 0; nt < 4; nt++)
#pragma unroll
                for (int c = 0; c < 4; c++) sacc[mt][nt][c] = 0.f;

        const uint32_t* Qb = sm + QS_OFF + (wm * 32) * 68;
        const uint32_t* Kb = sm + KS_OFF + (wn * 32) * 68;
#pragma unroll
        for (int ks = 0; ks < 8; ks++) {
            const int kb = ks * 8;
            uint32_t a[2][4];
#pragma unroll
            for (int mt = 0; mt < 2; mt++) {
                const uint32_t* Qr = Qb + mt * 16 * 68;
                a[mt][0] = Qr[g * 68 + kb + t];
                a[mt][1] = Qr[(g + 8) * 68 + kb + t];
                a[mt][2] = Qr[g * 68 + kb + t + 4];
                a[mt][3] = Qr[(g + 8) * 68 + kb + t + 4];
            }
#pragma unroll
            for (int nt = 0; nt < 4; nt++) {
                uint32_t b0 = Kb[(nt * 8 + g) * 68 + kb + t];
                uint32_t b1 = Kb[(nt * 8 + g) * 68 + kb + t + 4];
                mma_fp16(sacc[0][nt], a[0], b0, b1);
                mma_fp16(sacc[1][nt], a[1], b0, b1);
            }
        }

        if (kvt >= 2 * qb) {
            const int off = (kvt - 2 * qb) * 64;
#pragma unroll
            for (int mt = 0; mt < 2; mt++) {
                int r0 = wm * 32 + mt * 16 + g, r1 = r0 + 8;
#pragma unroll
                for (int nt = 0; nt < 4; nt++) {
                    int c = wn * 32 + nt * 8 + 2 * t + off;
                    if (c     > r0) sacc[mt][nt][0] = -1e30f;
                    if (c + 1 > r0) sacc[mt][nt][1] = -1e30f;
                    if (c     > r1) sacc[mt][nt][2] = -1e30f;
                    if (c + 1 > r1) sacc[mt][nt][3] = -1e30f;
                }
            }
        }

#pragma unroll
        for (int mt = 0; mt < 2; mt++) {
            float rm0 = -1e30f, rm1 = -1e30f;
#pragma unroll
            for (int nt = 0; nt < 4; nt++) {
                rm0 = fmaxf(rm0, fmaxf(sacc[mt][nt][0], sacc[mt][nt][1]));
                rm1 = fmaxf(rm1, fmaxf(sacc[mt][nt][2], sacc[mt][nt][3]));
            }
            rm0 = fmaxf(rm0, __shfl_xor_sync(0xffffffffu, rm0, 1));
            rm0 = fmaxf(rm0, __shfl_xor_sync(0xffffffffu, rm0, 2));
            rm1 = fmaxf(rm1, __shfl_xor_sync(0xffffffffu, rm1, 1));
            rm1 = fmaxf(rm1, __shfl_xor_sync(0xffffffffu, rm1, 2));
            if (t == 0) {
                pmax[wn * 128 + wm * 32 + mt * 16 + g]     = rm0;
                pmax[wn * 128 + wm * 32 + mt * 16 + g + 8] = rm1;
            }
        }
        asm volatile("bar.sync %0, 64;" :: "r"(bar_id) : "memory");

        float alpha[2][2], mnew[2][2];
#pragma unroll
        for (int mt = 0; mt < 2; mt++) {
            int r0 = wm * 32 + mt * 16 + g, r1 = r0 + 8;
            float mo0 = m_s[r0], mo1 = m_s[r1];
            float mn0 = fmaxf(mo0, fmaxf(pmax[r0], pmax[128 + r0]));
            float mn1 = fmaxf(mo1, fmaxf(pmax[r1], pmax[128 + r1]));
            alpha[mt][0] = __expf(mo0 - mn0);
            alpha[mt][1] = __expf(mo1 - mn1);
            mnew[mt][0] = mn0; mnew[mt][1] = mn1;
            float rs0 = 0.f, rs1 = 0.f;
#pragma unroll
            for (int nt = 0; nt < 4; nt++) {
                float p00 = __expf(sacc[mt][nt][0] - mn0);
                float p01 = __expf(sacc[mt][nt][1] - mn0);
                float p10 = __expf(sacc[mt][nt][2] - mn1);
                float p11 = __expf(sacc[mt][nt][3] - mn1);
                rs0 += p00 + p01;
                rs1 += p10 + p11;
                int w = wn * 16 + nt * 4 + t;
                sm[PS_OFF + r0 * 36 + w] = pack_h2(p00, p01);
                sm[PS_OFF + r1 * 36 + w] = pack_h2(p10, p11);
            }
            rs0 += __shfl_xor_sync(0xffffffffu, rs0, 1);
            rs0 += __shfl_xor_sync(0xffffffffu, rs0, 2);
            rs1 += __shfl_xor_sync(0xffffffffu, rs1, 1);
            rs1 += __shfl_xor_sync(0xffffffffu, rs1, 2);
            if (t == 0) {
                psum[wn * 128 + r0] = rs0;
                psum[wn * 128 + r1] = rs1;
            }
        }
#pragma unroll
        for (int mt = 0; mt < 2; mt++)
#pragma unroll
            for (int nt = 0; nt < 8; nt++) {
                oacc[mt][nt][0] *= alpha[mt][0];
                oacc[mt][nt][1] *= alpha[mt][0];
                oacc[mt][nt][2] *= alpha[mt][1];
                oacc[mt][nt][3] *= alpha[mt][1];
            }
        asm volatile("bar.sync %0, 64;" :: "r"(bar_id) : "memory");
        if (wn == 0 && t == 0) {
#pragma unroll
            for (int mt = 0; mt < 2; mt++) {
                int r0 = wm * 32 + mt * 16 + g, r1 = r0 + 8;
                l_s[r0] = l_s[r0] * alpha[mt][0] + psum[r0] + psum[128 + r0];
                l_s[r1] = l_s[r1] * alpha[mt][1] + psum[r1] + psum[128 + r1];
                m_s[r0] = mnew[mt][0];
                m_s[r1] = mnew[mt][1];
            }
        }

        __syncthreads();
        if (kvt + 1 < nkv) {
            const __half* kn = kbase + (size_t)(kvt + 1) * 64 * HD;
            const __half* vn = vbase + (size_t)(kvt + 1) * 64 * HD;
            const uint32_t vo = cur ? VS_OFF0 : VS_OFF1;
#pragma unroll
            for (int i = 0; i < 4; i++) {
                int id = tid + 256 * i;
                int row = id >> 4, c = id & 15;
                cpa16(smb + (KS_OFF + row * 68 + c * 4) * 4, kn + (size_t)row * HD + c * 8);
            }
#pragma unroll
            for (int i = 0; i < 4; i++) {
                int id = tid + 256 * i;
                int row = id >> 5, c = id & 31;
                cpa16(smb + (vo + row * 136 + c * 4) * 4, vn + (size_t)row * 256 + c * 8);
            }
            asm volatile("cp.async.commit_group;");
        }

        const uint32_t* Pb = sm + PS_OFF + (wm * 32) * 36;
        const uint32_t* Vb = sm + (cur ? VS_OFF1 : VS_OFF0) + wn * 64;
#pragma unroll
        for (int ks = 0; ks < 4; ks++) {
            const int kb = ks * 8;
            uint32_t a[2][4];
#pragma unroll
            for (int mt = 0; mt < 2; mt++) {
                const uint32_t* Pr = Pb + mt * 16 * 36;
                a[mt][0] = Pr[g * 36 + kb + t];
                a[mt][1] = Pr[(g + 8) * 36 + kb + t];
                a[mt][2] = Pr[g * 36 + kb + t + 4];
                a[mt][3] = Pr[(g + 8) * 36 + kb + t + 4];
            }
#pragma unroll
            for (int nt = 0; nt < 8; nt++) {
                uint32_t b0 = Vb[(kb + t) * 136 + nt * 8 + g];
                uint32_t b1 = Vb[(kb + t + 4) * 136 + nt * 8 + g];
                mma_fp16(oacc[0][nt], a[0], b0, b1);
                mma_fp16(oacc[1][nt], a[1], b0, b1);
            }
        }

        if (kvt + 1 < nkv) {
            asm volatile("cp.async.wait_group 0;");
            __syncthreads();
        }
    }

    asm volatile("bar.sync %0, 64;" :: "r"(bar_id) : "memory");

#pragma unroll
    for (int mt = 0; mt < 2; mt++) {
        int r0 = wm * 32 + mt * 16 + g, r1 = r0 + 8;
        float linv0 = 1.0f / l_s[r0];
        float linv1 = 1.0f / l_s[r1];
        uint32_t* y0 = y + ((size_t)b * SS + (size_t)qb * 128 + r0) * (DIM / 2)
                         + h * (HD / 2) + wn * 32;
        uint32_t* y1 = y + ((size_t)b * SS + (size_t)qb * 128 + r1) * (DIM / 2)
                         + h * (HD / 2) + wn * 32;
#pragma unroll
        for (int nt = 0; nt < 8; nt++) {
            y0[nt * 4 + t] = pack_h2(oacc[mt][nt][0] * linv0,
                                     oacc[mt][nt][1] * linv0);
            y1[nt * 4 + t] = pack_h2(oacc[mt][nt][2] * linv1,
                                     oacc[mt][nt][3] * linv1);
        }
    }
}

// =====================================================================
// host
// =====================================================================
extern "C" void kernel_launch(void* const* d_in, const int* in_sizes, int n_in,
                              void* d_out, int out_size)
{
    const float* x     = (const float*)d_in[0];
    const float* Wq    = (const float*)d_in[1];
    const float* Wk    = (const float*)d_in[2];
    const float* Wv    = (const float*)d_in[3];
    const float* Wproj = (const float*)d_in[4];
    const float* qg    = (const float*)d_in[5];
    float* out = (float*)d_out;

    __half *qh, *kh, *vh;
    uint32_t *y, *xt, *wt, *wpt;
    cudaGetSymbolAddress((void**)&qh,  g_qh);
    cudaGetSymbolAddress((void**)&kh,  g_kh);
    cudaGetSymbolAddress((void**)&vh,  g_vh);
    cudaGetSymbolAddress((void**)&y,   g_y);
    cudaGetSymbolAddress((void**)&xt,  g_xt);
    cudaGetSymbolAddress((void**)&wt,  g_wt);
    cudaGetSymbolAddress((void**)&wpt, g_wpt);

    cudaFuncSetAttribute(attn_mma,
                         cudaFuncAttributeMaxDynamicSharedMemorySize,
                         ATTN_WORDS * sizeof(uint32_t));
    cudaFuncSetAttribute(gemm_fp16_t<true>,
                         cudaFuncAttributeMaxDynamicSharedMemorySize,
                         GEMM_SMEM_BYTES);
    cudaFuncSetAttribute(gemm_fp16_t<false>,
                         cudaFuncAttributeMaxDynamicSharedMemorySize,
                         GEMM_SMEM_BYTES);

    // (0) RoPE tables
    rope_init<<<SS * 32 / 256, 256>>>();
    // (1) convert x -> fp16
    to_fp16<<<(MROWS * DIM / 4 + 255) / 256, 256>>>((const float4*)x, (uint2*)xt, MROWS * DIM / 4);
    // (2) convert Wq|Wk|Wv -> fp16
    to_fp16_w3<<<(QKVD * DIM / 4) / 256, 256>>>(
        (const float4*)Wq, (const float4*)Wk, (const float4*)Wv, (uint2*)wt);

    // (3) fused QKV projection + RMS-norm + RoPE -> q/k/v fp16  <-- ncu
    gemm_fp16_t<true><<<dim3(QKVD / 128, MROWS / 128), 256, GEMM_SMEM_BYTES>>>(
        xt, wt, nullptr, qg, DIM, 0, 0);

    // (4) fp16 flash attention -> g_y
    attn_mma<<<dim3(SS / 128, NH, BB), 256,
               ATTN_WORDS * sizeof(uint32_t)>>>(qh, kh, vh, y);

    // (5) convert Wproj -> fp16
    to_fp16<<<(DIM * DIM / 4 + 255) / 256, 256>>>((const float4*)Wproj, (uint2*)wpt, DIM * DIM / 4);

    // (6) output projection -> d_out
    gemm_fp16_t<false><<<dim3(DIM / 128, MROWS / 128), 256, GEMM_SMEM_BYTES>>>(
        y, wpt, out, qg, DIM, DIM, 0);
}

// round 15
// speedup vs baseline: 2.0438x; 1.0950x over previous
#include <cuda_runtime.h>
#include <cuda_fp16.h>
#include <math.h>
#include <stdint.h>

#define DIM 2048
#define NH 16
#define NKV 4
#define HD 128
#define BB 4
#define SS 2048
#define KVD 512        // NKV*HD
#define QKVD 3072      // DIM + 2*KVD
#define MROWS (BB*SS)  // 8192
#define ATTN_SCALE 0.08838834764831845f  // 1/sqrt(128)

// ---------------- scratch (no allocations allowed) ----------------
__device__ __half   g_qh[(size_t)BB*NH*SS*HD];     // fp16 q (scale folded)
__device__ __half   g_kh[(size_t)BB*NKV*SS*HD];    // fp16 k
__device__ __half   g_vh[(size_t)BB*NKV*SS*HD];    // fp16 v, s-paired layout
__device__ uint32_t g_y[(size_t)BB*SS*DIM/2];      // fp16x2 (attn out)
__device__ uint32_t g_xt[(size_t)MROWS*DIM/2];     // fp16x2 of x
__device__ uint32_t g_wt[(size_t)QKVD*DIM/2];      // fp16x2 Wq|Wk|Wv
__device__ uint32_t g_wpt[(size_t)DIM*DIM/2];      // fp16x2 Wproj
__device__ float    g_cosr[SS*32];
__device__ float    g_sinr[SS*32];

// =====================================================================
// helpers
// =====================================================================
__device__ __forceinline__ void mma_fp16(float* c, const uint32_t* a,
                                         uint32_t b0, uint32_t b1) {
    asm volatile(
        "mma.sync.aligned.m16n8k16.row.col.f32.f16.f16.f32 "
        "{%0,%1,%2,%3}, {%4,%5,%6,%7}, {%8,%9}, {%0,%1,%2,%3};"
        : "+f"(c[0]), "+f"(c[1]), "+f"(c[2]), "+f"(c[3])
        : "r"(a[0]), "r"(a[1]), "r"(a[2]), "r"(a[3]), "r"(b0), "r"(b1));
}

__device__ __forceinline__ void ldsm4(uint32_t* r, uint32_t addr) {
    asm volatile("ldmatrix.sync.aligned.m8n8.x4.shared.b16 {%0,%1,%2,%3}, [%4];"
                 : "=r"(r[0]), "=r"(r[1]), "=r"(r[2]), "=r"(r[3]) : "r"(addr));
}

__device__ __forceinline__ void cpa16(uint32_t dst, const void* src) {
    asm volatile("cp.async.cg.shared.global [%0], [%1], 16;"
                 :: "r"(dst), "l"(src));
}

__device__ __forceinline__ uint32_t pack_h2(float x, float y) {
    __half2 h = __floats2half2_rn(x, y);
    return *(uint32_t*)&h;
}

// =====================================================================
// elementwise fp32 -> fp16x2 conversions
// =====================================================================
__global__ void to_fp16(const float4* __restrict__ src,
                        uint2* __restrict__ dst, int n4)
{
    int i = blockIdx.x * blockDim.x + threadIdx.x;
    if (i < n4) {
        float4 v = src[i];
        dst[i] = make_uint2(pack_h2(v.x, v.y), pack_h2(v.z, v.w));
    }
}

__global__ void to_fp16_w3(const float4* __restrict__ wq,
                           const float4* __restrict__ wk,
                           const float4* __restrict__ wv,
                           uint2* __restrict__ dst)
{
    int i = blockIdx.x * blockDim.x + threadIdx.x;
    const int nq = DIM * DIM / 4;
    const int nk = KVD * DIM / 4;
    float4 v;
    if (i < nq)            v = wq[i];
    else if (i < nq + nk)  v = wk[i - nq];
    else                   v = wv[i - nq - nk];
    dst[i] = make_uint2(pack_h2(v.x, v.y), pack_h2(v.z, v.w));
}

// =====================================================================
// RoPE table init
// =====================================================================
__global__ void rope_init()
{
    int i = blockIdx.x * blockDim.x + threadIdx.x;
    int s = i >> 5, f = i & 31;
    double inv = pow(10000.0, -(double)f / 32.0);
    double ang = (double)s * inv;
    double sd, cd;
    sincos(ang, &sd, &cd);
    g_cosr[i] = (float)cd;
    g_sinr[i] = (float)sd;
}

// =====================================================================
// fp16 warp-mma GEMM, 128x128x32 tiles, 3-stage cp.async, LDMATRIX
// fragment loads (6 LSU ops per k16 step instead of 24).
// FUSE=0: plain fp32 C output. FUSE=1: fused RMS-norm+RoPE QKV epilogue.
// =====================================================================
#define SH 20
#define GSTG_W 5120
#define GEMM_SMEM_BYTES 61440

template<bool FUSE>
__global__ __launch_bounds__(256, 2)
void gemm_fp16_t(const uint32_t* __restrict__ A, const uint32_t* __restrict__ W,
                 float* __restrict__ C, const float* __restrict__ qg,
                 int K, int ldc, int coloff)
{
    extern __shared__ uint32_t sm[];
    const int KW   = K >> 1;
    const int tid  = threadIdx.x;
    const int lane = tid & 31;
    const int wid  = tid >> 5;
    const int wm   = wid & 3;
    const int wn   = wid >> 2;
    const int g    = lane >> 2;
    const int t    = lane & 3;
    const int m0   = blockIdx.y * 128;
    const int n0   = blockIdx.x * 128;
    const uint32_t smb = (uint32_t)__cvta_generic_to_shared(sm);

    // ldmatrix per-lane address offsets (in words, stage-relative)
    const int rowA = lane & 15;
    const int aK   = (lane >> 4) << 2;               // +0 / +4 words (k high 8)
    uint32_t aoff[2];
    aoff[0] = (uint32_t)((wm * 32 + rowA) * SH + aK);
    aoff[1] = aoff[0] + 16 * SH;
    const int bn = (lane & 7) + ((lane & 16) >> 1);  // 0..15 within n16
    const int bK = ((lane >> 3) & 1) << 2;
    uint32_t boff[4];
#pragma unroll
    for (int p = 0; p < 4; p++)
        boff[p] = (uint32_t)(2560 + (wn * 64 + p * 16 + bn) * SH + bK);

    float acc[2][8][4];
#pragma unroll
    for (int mt = 0; mt < 2; mt++)
#pragma unroll
        for (int nt = 0; nt < 8; nt++)
#pragma unroll
            for (int c = 0; c < 4; c++) acc[mt][nt][c] = 0.f;

    const int ntile = K >> 5;

    auto load_tile = [&](int it, int s) {
        const uint32_t base = (uint32_t)s * GSTG_W;
        const size_t kwb = (size_t)it * 16;
#pragma unroll
        for (int r = 0; r < 2; r++) {
            int id = tid + 256 * r;
            int row = id >> 2, c4 = (id & 3) * 4;
            cpa16(smb + (base + row * SH + c4) * 4,
                  A + (size_t)(m0 + row) * KW + kwb + c4);
            cpa16(smb + (base + 2560 + row * SH + c4) * 4,
                  W + (size_t)(n0 + row) * KW + kwb + c4);
        }
        asm volatile("cp.async.commit_group;");
    };

    load_tile(0, 0);
    load_tile(1, 1);

    int s = 0;
    for (int it = 0; it < ntile; it++) {
        if (it + 1 < ntile) {
            asm volatile("cp.async.wait_group 1;");
        } else {
            asm volatile("cp.async.wait_group 0;");
        }
        __syncthreads();

        if (it + 2 < ntile) {
            int s2 = s + 2; if (s2 >= 3) s2 -= 3;
            load_tile(it + 2, s2);
        }

        const uint32_t sb4 = smb + (uint32_t)s * GSTG_W * 4;
#pragma unroll
        for (int h = 0; h < 2; h++) {
            const uint32_t kb4 = (uint32_t)(h * 8) * 4;
            uint32_t a[2][4];
            ldsm4(a[0], sb4 + aoff[0] * 4 + kb4);
            ldsm4(a[1], sb4 + aoff[1] * 4 + kb4);
#pragma unroll
            for (int p = 0; p < 4; p++) {
                uint32_t bq[4];
                ldsm4(bq, sb4 + boff[p] * 4 + kb4);
                mma_fp16(acc[0][p * 2    ], a[0], bq[0], bq[1]);
                mma_fp16(acc[1][p * 2    ], a[1], bq[0], bq[1]);
                mma_fp16(acc[0][p * 2 + 1], a[0], bq[2], bq[3]);
                mma_fp16(acc[1][p * 2 + 1], a[1], bq[2], bq[3]);
            }
        }
        if (++s >= 3) s = 0;
    }

    if (!FUSE) {
#pragma unroll
        for (int mt = 0; mt < 2; mt++) {
            int row = m0 + wm * 32 + mt * 16 + g;
#pragma unroll
            for (int nt = 0; nt < 8; nt++) {
                int col = coloff + n0 + wn * 64 + nt * 8 + 2 * t;
                float2 v01 = make_float2(acc[mt][nt][0], acc[mt][nt][1]);
                float2 v23 = make_float2(acc[mt][nt][2], acc[mt][nt][3]);
                *(float2*)(C + (size_t)row * ldc + col)       = v01;
                *(float2*)(C + (size_t)(row + 8) * ldc + col) = v23;
            }
        }
        return;
    }

    // ================= FUSED norm+rope epilogue (QKV) =================
    const int head  = n0 >> 7;
    const int bq    = m0 >> 11;
    const int sbase = m0 & (SS - 1);
    float* red = (float*)sm;

    float ss[2][2];
#pragma unroll
    for (int mt = 0; mt < 2; mt++) { ss[mt][0] = 0.f; ss[mt][1] = 0.f; }
#pragma unroll
    for (int mt = 0; mt < 2; mt++)
#pragma unroll
        for (int nt = 0; nt < 8; nt++) {
            ss[mt][0] += acc[mt][nt][0] * acc[mt][nt][0]
                       + acc[mt][nt][1] * acc[mt][nt][1];
            ss[mt][1] += acc[mt][nt][2] * acc[mt][nt][2]
                       + acc[mt][nt][3] * acc[mt][nt][3];
        }
#pragma unroll
    for (int mt = 0; mt < 2; mt++)
#pragma unroll
        for (int hf = 0; hf < 2; hf++) {
            ss[mt][hf] += __shfl_xor_sync(0xffffffffu, ss[mt][hf], 1);
            ss[mt][hf] += __shfl_xor_sync(0xffffffffu, ss[mt][hf], 2);
        }

    __syncthreads();
    if (t == 0) {
#pragma unroll
        for (int mt = 0; mt < 2; mt++) {
            red[wn * 128 + wm * 32 + mt * 16 + g]     = ss[mt][0];
            red[wn * 128 + wm * 32 + mt * 16 + g + 8] = ss[mt][1];
        }
    }
    __syncthreads();

    const float gscale = (head < 16) ? qg[head] * ATTN_SCALE : 1.0f;

#pragma unroll
    for (int mt = 0; mt < 2; mt++) {
#pragma unroll
        for (int hf = 0; hf < 2; hf++) {
            const int r  = wm * 32 + mt * 16 + g + hf * 8;
            const int sg = sbase + r;

            float vv[8][2];
            if (head < 20) {
                float sum = red[r] + red[128 + r];
                float rinv = rsqrtf(sum * (1.0f / HD) + 1.1920929e-07f) * gscale;
#pragma unroll
                for (int nt = 0; nt < 8; nt++) {
                    vv[nt][0] = acc[mt][nt][hf * 2 + 0] * rinv;
                    vv[nt][1] = acc[mt][nt][hf * 2 + 1] * rinv;
                }
                if (wn == 0) {
#pragma unroll
                    for (int nt = 0; nt < 4; nt++)
#pragma unroll
                        for (int j = 0; j < 2; j++) {
                            int f = nt * 8 + 2 * t + j;
                            float c  = g_cosr[sg * 32 + f];
                            float sn = g_sinr[sg * 32 + f];
                            float x1 = vv[nt][j], x2 = vv[nt + 4][j];
                            vv[nt][j]     =  x1 * c + x2 * sn;
                            vv[nt + 4][j] = -x1 * sn + x2 * c;
                        }
                }
                __half* dst = (head < 16)
                    ? g_qh + ((size_t)(bq * NH + head) * SS + sg) * HD
                    : g_kh + ((size_t)(bq * NKV + head - 16) * SS + sg) * HD;
                dst += wn * 64;
#pragma unroll
                for (int nt = 0; nt < 8; nt++)
                    *(uint32_t*)(dst + nt * 8 + 2 * t) = pack_h2(vv[nt][0], vv[nt][1]);
            } else {
                __half* dst = g_vh + (size_t)(bq * NKV + head - 20) * SS * HD
                            + (size_t)(sg & ~1) * HD + (sg & 1) + (size_t)wn * 128;
#pragma unroll
                for (int nt = 0; nt < 8; nt++) {
                    int c0 = nt * 8 + 2 * t;
                    dst[2 * c0]     = __float2half_rn(acc[mt][nt][hf * 2 + 0]);
                    dst[2 * c0 + 2] = __float2half_rn(acc[mt][nt][hf * 2 + 1]);
                }
            }
        }
    }
}

// =====================================================================
// fp16 flash attention (R12/R13 winner, unchanged)
// =====================================================================
#define QS_OFF   0            // 128 x 68
#define KS_OFF   8704         // 64 x 68
#define VS_OFF0  13056        // 32 x 136
#define VS_OFF1  17408
#define PS_OFF   21760        // 128 x 36
#define PMAX_OFF 26368        // [2][128]
#define PSUM_OFF 26624        // [2][128]
#define MS_OFF   26880        // [128]
#define LS_OFF   27008        // [128]
#define ATTN_WORDS 27136      // 108,544 bytes

__global__ __launch_bounds__(256, 2)
void attn_mma(const __half* __restrict__ q, const __half* __restrict__ k,
              const __half* __restrict__ v, uint32_t* __restrict__ y)
{
    extern __shared__ uint32_t sm[];
    const int qb = (int)gridDim.x - 1 - (int)blockIdx.x;
    const int h = blockIdx.y, b = blockIdx.z;
    const int kvh = h >> 2;
    const int tid = threadIdx.x;
    const int lane = tid & 31, wid = tid >> 5;
    const int g = lane >> 2, t = lane & 3;
    const int wm = wid & 3, wn = wid >> 2;
    const int bar_id = 1 + wm;

    const __half* qbase = q + ((size_t)(b * NH + h) * SS + (size_t)qb * 128) * HD;
    const __half* kbase = k + ((size_t)(b * NKV + kvh) * SS) * HD;
    const __half* vbase = v + ((size_t)(b * NKV + kvh) * SS) * HD;  // paired

    const uint32_t smb = (uint32_t)__cvta_generic_to_shared(sm);

    float* m_s  = (float*)(sm + MS_OFF);
    float* l_s  = (float*)(sm + LS_OFF);
    float* pmax = (float*)(sm + PMAX_OFF);
    float* psum = (float*)(sm + PSUM_OFF);

#pragma unroll
    for (int i = 0; i < 8; i++) {
        int id = tid + 256 * i;
        int row = id >> 4, c = id & 15;
        cpa16(smb + (QS_OFF + row * 68 + c * 4) * 4, qbase + (size_t)row * HD + c * 8);
    }
#pragma unroll
    for (int i = 0; i < 4; i++) {
        int id = tid + 256 * i;
        int row = id >> 4, c = id & 15;
        cpa16(smb + (KS_OFF + row * 68 + c * 4) * 4, kbase + (size_t)row * HD + c * 8);
    }
#pragma unroll
    for (int i = 0; i < 4; i++) {
        int id = tid + 256 * i;
        int row = id >> 5, c = id & 31;
        cpa16(smb + (VS_OFF0 + row * 136 + c * 4) * 4, vbase + (size_t)row * 256 + c * 8);
    }
    asm volatile("cp.async.commit_group;");

    if (tid < 128) { m_s[tid] = -1e30f; l_s[tid] = 0.f; }

    float oacc[2][8][4];
#pragma unroll
    for (int mt = 0; mt < 2; mt++)
#pragma unroll
        for (int nt = 0; nt < 8; nt++)
#pragma unroll
            for (int c = 0; c < 4; c++) oacc[mt][nt][c] = 0.f;

    const int nkv = 2 * qb + 2;

    asm volatile("cp.async.wait_group 0;");
    __syncthreads();

    for (int kvt = 0; kvt < nkv; kvt++) {
        const int cur = kvt & 1;

        float sacc[2][4][4];
#pragma unroll
        for (int mt = 0; mt < 2; mt++)
#pragma unroll
            for (int nt = 0; nt < 4; nt++)
#pragma unroll
                for (int c = 0; c < 4; c++) sacc[mt][nt][c] = 0.f;

        const uint32_t* Qb = sm + QS_OFF + (wm * 32) * 68;
        const uint32_t* Kb = sm + KS_OFF + (wn * 32) * 68;
#pragma unroll
        for (int ks = 0; ks < 8; ks++) {
            const int kb = ks * 8;
            uint32_t a[2][4];
#pragma unroll
            for (int mt = 0; mt < 2; mt++) {
                const uint32_t* Qr = Qb + mt * 16 * 68;
                a[mt][0] = Qr[g * 68 + kb + t];
                a[mt][1] = Qr[(g + 8) * 68 + kb + t];
                a[mt][2] = Qr[g * 68 + kb + t + 4];
                a[mt][3] = Qr[(g + 8) * 68 + kb + t + 4];
            }
#pragma unroll
            for (int nt = 0; nt < 4; nt++) {
                uint32_t b0 = Kb[(nt * 8 + g) * 68 + kb + t];
                uint32_t b1 = Kb[(nt * 8 + g) * 68 + kb + t + 4];
                mma_fp16(sacc[0][nt], a[0], b0, b1);
                mma_fp16(sacc[1][nt], a[1], b0, b1);
            }
        }

        if (kvt >= 2 * qb) {
            const int off = (kvt - 2 * qb) * 64;
#pragma unroll
            for (int mt = 0; mt < 2; mt++) {
                int r0 = wm * 32 + mt * 16 + g, r1 = r0 + 8;
#pragma unroll
                for (int nt = 0; nt < 4; nt++) {
                    int c = wn * 32 + nt * 8 + 2 * t + off;
                    if (c     > r0) sacc[mt][nt][0] = -1e30f;
                    if (c + 1 > r0) sacc[mt][nt][1] = -1e30f;
                    if (c     > r1) sacc[mt][nt][2] = -1e30f;
                    if (c + 1 > r1) sacc[mt][nt][3] = -1e30f;
                }
            }
        }

#pragma unroll
        for (int mt = 0; mt < 2; mt++) {
            float rm0 = -1e30f, rm1 = -1e30f;
#pragma unroll
            for (int nt = 0; nt < 4; nt++) {
                rm0 = fmaxf(rm0, fmaxf(sacc[mt][nt][0], sacc[mt][nt][1]));
                rm1 = fmaxf(rm1, fmaxf(sacc[mt][nt][2], sacc[mt][nt][3]));
            }
            rm0 = fmaxf(rm0, __shfl_xor_sync(0xffffffffu, rm0, 1));
            rm0 = fmaxf(rm0, __shfl_xor_sync(0xffffffffu, rm0, 2));
            rm1 = fmaxf(rm1, __shfl_xor_sync(0xffffffffu, rm1, 1));
            rm1 = fmaxf(rm1, __shfl_xor_sync(0xffffffffu, rm1, 2));
            if (t == 0) {
                pmax[wn * 128 + wm * 32 + mt * 16 + g]     = rm0;
                pmax[wn * 128 + wm * 32 + mt * 16 + g + 8] = rm1;
            }
        }
        asm volatile("bar.sync %0, 64;" :: "r"(bar_id) : "memory");

        float alpha[2][2], mnew[2][2];
#pragma unroll
        for (int mt = 0; mt < 2; mt++) {
            int r0 = wm * 32 + mt * 16 + g, r1 = r0 + 8;
            float mo0 = m_s[r0], mo1 = m_s[r1];
            float mn0 = fmaxf(mo0, fmaxf(pmax[r0], pmax[128 + r0]));
            float mn1 = fmaxf(mo1, fmaxf(pmax[r1], pmax[128 + r1]));
            alpha[mt][0] = __expf(mo0 - mn0);
            alpha[mt][1] = __expf(mo1 - mn1);
            mnew[mt][0] = mn0; mnew[mt][1] = mn1;
            float rs0 = 0.f, rs1 = 0.f;
#pragma unroll
            for (int nt = 0; nt < 4; nt++) {
                float p00 = __expf(sacc[mt][nt][0] - mn0);
                float p01 = __expf(sacc[mt][nt][1] - mn0);
                float p10 = __expf(sacc[mt][nt][2] - mn1);
                float p11 = __expf(sacc[mt][nt][3] - mn1);
                rs0 += p00 + p01;
                rs1 += p10 + p11;
                int w = wn * 16 + nt * 4 + t;
                sm[PS_OFF + r0 * 36 + w] = pack_h2(p00, p01);
                sm[PS_OFF + r1 * 36 + w] = pack_h2(p10, p11);
            }
            rs0 += __shfl_xor_sync(0xffffffffu, rs0, 1);
            rs0 += __shfl_xor_sync(0xffffffffu, rs0, 2);
            rs1 += __shfl_xor_sync(0xffffffffu, rs1, 1);
            rs1 += __shfl_xor_sync(0xffffffffu, rs1, 2);
            if (t == 0) {
                psum[wn * 128 + r0] = rs0;
                psum[wn * 128 + r1] = rs1;
            }
        }
#pragma unroll
        for (int mt = 0; mt < 2; mt++)
#pragma unroll
            for (int nt = 0; nt < 8; nt++) {
                oacc[mt][nt][0] *= alpha[mt][0];
                oacc[mt][nt][1] *= alpha[mt][0];
                oacc[mt][nt][2] *= alpha[mt][1];
                oacc[mt][nt][3] *= alpha[mt][1];
            }
        asm volatile("bar.sync %0, 64;" :: "r"(bar_id) : "memory");
        if (wn == 0 && t == 0) {
#pragma unroll
            for (int mt = 0; mt < 2; mt++) {
                int r0 = wm * 32 + mt * 16 + g, r1 = r0 + 8;
                l_s[r0] = l_s[r0] * alpha[mt][0] + psum[r0] + psum[128 + r0];
                l_s[r1] = l_s[r1] * alpha[mt][1] + psum[r1] + psum[128 + r1];
                m_s[r0] = mnew[mt][0];
                m_s[r1] = mnew[mt][1];
            }
        }

        __syncthreads();
        if (kvt + 1 < nkv) {
            const __half* kn = kbase + (size_t)(kvt + 1) * 64 * HD;
            const __half* vn = vbase + (size_t)(kvt + 1) * 64 * HD;
            const uint32_t vo = cur ? VS_OFF0 : VS_OFF1;
#pragma unroll
            for (int i = 0; i < 4; i++) {
                int id = tid + 256 * i;
                int row = id >> 4, c = id & 15;
                cpa16(smb + (KS_OFF + row * 68 + c * 4) * 4, kn + (size_t)row * HD + c * 8);
            }
#pragma unroll
            for (int i = 0; i < 4; i++) {
                int id = tid + 256 * i;
                int row = id >> 5, c = id & 31;
                cpa16(smb + (vo + row * 136 + c * 4) * 4, vn + (size_t)row * 256 + c * 8);
            }
            asm volatile("cp.async.commit_group;");
        }

        const uint32_t* Pb = sm + PS_OFF + (wm * 32) * 36;
        const uint32_t* Vb = sm + (cur ? VS_OFF1 : VS_OFF0) + wn * 64;
#pragma unroll
        for (int ks = 0; ks < 4; ks++) {
            const int kb = ks * 8;
            uint32_t a[2][4];
#pragma unroll
            for (int mt = 0; mt < 2; mt++) {
                const uint32_t* Pr = Pb + mt * 16 * 36;
                a[mt][0] = Pr[g * 36 + kb + t];
                a[mt][1] = Pr[(g + 8) * 36 + kb + t];
                a[mt][2] = Pr[g * 36 + kb + t + 4];
                a[mt][3] = Pr[(g + 8) * 36 + kb + t + 4];
            }
#pragma unroll
            for (int nt = 0; nt < 8; nt++) {
                uint32_t b0 = Vb[(kb + t) * 136 + nt * 8 + g];
                uint32_t b1 = Vb[(kb + t + 4) * 136 + nt * 8 + g];
                mma_fp16(oacc[0][nt], a[0], b0, b1);
                mma_fp16(oacc[1][nt], a[1], b0, b1);
            }
        }

        if (kvt + 1 < nkv) {
            asm volatile("cp.async.wait_group 0;");
            __syncthreads();
        }
    }

    asm volatile("bar.sync %0, 64;" :: "r"(bar_id) : "memory");

#pragma unroll
    for (int mt = 0; mt < 2; mt++) {
        int r0 = wm * 32 + mt * 16 + g, r1 = r0 + 8;
        float linv0 = 1.0f / l_s[r0];
        float linv1 = 1.0f / l_s[r1];
        uint32_t* y0 = y + ((size_t)b * SS + (size_t)qb * 128 + r0) * (DIM / 2)
                         + h * (HD / 2) + wn * 32;
        uint32_t* y1 = y + ((size_t)b * SS + (size_t)qb * 128 + r1) * (DIM / 2)
                         + h * (HD / 2) + wn * 32;
#pragma unroll
        for (int nt = 0; nt < 8; nt++) {
            y0[nt * 4 + t] = pack_h2(oacc[mt][nt][0] * linv0,
                                     oacc[mt][nt][1] * linv0);
            y1[nt * 4 + t] = pack_h2(oacc[mt][nt][2] * linv1,
                                     oacc[mt][nt][3] * linv1);
        }
    }
}

// =====================================================================
// host
// =====================================================================
extern "C" void kernel_launch(void* const* d_in, const int* in_sizes, int n_in,
                              void* d_out, int out_size)
{
    const float* x     = (const float*)d_in[0];
    const float* Wq    = (const float*)d_in[1];
    const float* Wk    = (const float*)d_in[2];
    const float* Wv    = (const float*)d_in[3];
    const float* Wproj = (const float*)d_in[4];
    const float* qg    = (const float*)d_in[5];
    float* out = (float*)d_out;

    __half *qh, *kh, *vh;
    uint32_t *y, *xt, *wt, *wpt;
    cudaGetSymbolAddress((void**)&qh,  g_qh);
    cudaGetSymbolAddress((void**)&kh,  g_kh);
    cudaGetSymbolAddress((void**)&vh,  g_vh);
    cudaGetSymbolAddress((void**)&y,   g_y);
    cudaGetSymbolAddress((void**)&xt,  g_xt);
    cudaGetSymbolAddress((void**)&wt,  g_wt);
    cudaGetSymbolAddress((void**)&wpt, g_wpt);

    cudaFuncSetAttribute(attn_mma,
                         cudaFuncAttributeMaxDynamicSharedMemorySize,
                         ATTN_WORDS * sizeof(uint32_t));
    cudaFuncSetAttribute(gemm_fp16_t<true>,
                         cudaFuncAttributeMaxDynamicSharedMemorySize,
                         GEMM_SMEM_BYTES);
    cudaFuncSetAttribute(gemm_fp16_t<false>,
                         cudaFuncAttributeMaxDynamicSharedMemorySize,
                         GEMM_SMEM_BYTES);

    // (0) RoPE tables
    rope_init<<<SS * 32 / 256, 256>>>();
    // (1) convert x -> fp16
    to_fp16<<<(MROWS * DIM / 4 + 255) / 256, 256>>>((const float4*)x, (uint2*)xt, MROWS * DIM / 4);
    // (2) convert Wq|Wk|Wv -> fp16
    to_fp16_w3<<<(QKVD * DIM / 4) / 256, 256>>>(
        (const float4*)Wq, (const float4*)Wk, (const float4*)Wv, (uint2*)wt);

    // (3) fused QKV projection + RMS-norm + RoPE -> q/k/v fp16  <-- ncu
    gemm_fp16_t<true><<<dim3(QKVD / 128, MROWS / 128), 256, GEMM_SMEM_BYTES>>>(
        xt, wt, nullptr, qg, DIM, 0, 0);

    // (4) fp16 flash attention -> g_y
    attn_mma<<<dim3(SS / 128, NH, BB), 256,
               ATTN_WORDS * sizeof(uint32_t)>>>(qh, kh, vh, y);

    // (5) convert Wproj -> fp16
    to_fp16<<<(DIM * DIM / 4 + 255) / 256, 256>>>((const float4*)Wproj, (uint2*)wpt, DIM * DIM / 4);

    // (6) output projection -> d_out
    gemm_fp16_t<false><<<dim3(DIM / 128, MROWS / 128), 256, GEMM_SMEM_BYTES>>>(
        y, wpt, out, qg, DIM, DIM, 0);
}

// round 16
// speedup vs baseline: 2.0950x; 1.0251x over previous
#include <cuda_runtime.h>
#include <cuda_fp16.h>
#include <math.h>
#include <stdint.h>

#define DIM 2048
#define NH 16
#define NKV 4
#define HD 128
#define BB 4
#define SS 2048
#define KVD 512        // NKV*HD
#define QKVD 3072      // DIM + 2*KVD
#define MROWS (BB*SS)  // 8192
#define ATTN_SCALE 0.08838834764831845f  // 1/sqrt(128)

// ---------------- scratch (no allocations allowed) ----------------
__device__ __half   g_qh[(size_t)BB*NH*SS*HD];     // fp16 q (scale folded)
__device__ __half   g_kh[(size_t)BB*NKV*SS*HD];    // fp16 k
__device__ __half   g_vh[(size_t)BB*NKV*SS*HD];    // fp16 v, s-paired layout
__device__ uint32_t g_y[(size_t)BB*SS*DIM/2];      // fp16x2 (attn out)
__device__ uint32_t g_xt[(size_t)MROWS*DIM/2];     // fp16x2 of x
__device__ uint32_t g_wt[(size_t)QKVD*DIM/2];      // fp16x2 Wq|Wk|Wv
__device__ uint32_t g_wpt[(size_t)DIM*DIM/2];      // fp16x2 Wproj
__device__ float    g_cosr[SS*32];
__device__ float    g_sinr[SS*32];

// =====================================================================
// helpers
// =====================================================================
__device__ __forceinline__ void mma_fp16(float* c, const uint32_t* a,
                                         uint32_t b0, uint32_t b1) {
    asm volatile(
        "mma.sync.aligned.m16n8k16.row.col.f32.f16.f16.f32 "
        "{%0,%1,%2,%3}, {%4,%5,%6,%7}, {%8,%9}, {%0,%1,%2,%3};"
        : "+f"(c[0]), "+f"(c[1]), "+f"(c[2]), "+f"(c[3])
        : "r"(a[0]), "r"(a[1]), "r"(a[2]), "r"(a[3]), "r"(b0), "r"(b1));
}

__device__ __forceinline__ void ldsm4(uint32_t* r, uint32_t addr) {
    asm volatile("ldmatrix.sync.aligned.m8n8.x4.shared.b16 {%0,%1,%2,%3}, [%4];"
                 : "=r"(r[0]), "=r"(r[1]), "=r"(r[2]), "=r"(r[3]) : "r"(addr));
}

__device__ __forceinline__ void cpa16(uint32_t dst, const void* src) {
    asm volatile("cp.async.cg.shared.global [%0], [%1], 16;"
                 :: "r"(dst), "l"(src));
}

__device__ __forceinline__ uint32_t pack_h2(float x, float y) {
    __half2 h = __floats2half2_rn(x, y);
    return *(uint32_t*)&h;
}

// =====================================================================
// elementwise fp32 -> fp16x2 conversions
// =====================================================================
__global__ void to_fp16(const float4* __restrict__ src,
                        uint2* __restrict__ dst, int n4)
{
    int i = blockIdx.x * blockDim.x + threadIdx.x;
    if (i < n4) {
        float4 v = src[i];
        dst[i] = make_uint2(pack_h2(v.x, v.y), pack_h2(v.z, v.w));
    }
}

__global__ void to_fp16_w3(const float4* __restrict__ wq,
                           const float4* __restrict__ wk,
                           const float4* __restrict__ wv,
                           uint2* __restrict__ dst)
{
    int i = blockIdx.x * blockDim.x + threadIdx.x;
    const int nq = DIM * DIM / 4;
    const int nk = KVD * DIM / 4;
    float4 v;
    if (i < nq)            v = wq[i];
    else if (i < nq + nk)  v = wk[i - nq];
    else                   v = wv[i - nq - nk];
    dst[i] = make_uint2(pack_h2(v.x, v.y), pack_h2(v.z, v.w));
}

// =====================================================================
// RoPE table init
// =====================================================================
__global__ void rope_init()
{
    int i = blockIdx.x * blockDim.x + threadIdx.x;
    int s = i >> 5, f = i & 31;
    double inv = pow(10000.0, -(double)f / 32.0);
    double ang = (double)s * inv;
    double sd, cd;
    sincos(ang, &sd, &cd);
    g_cosr[i] = (float)cd;
    g_sinr[i] = (float)sd;
}

// =====================================================================
// fp16 warp-mma GEMM, 128x128x32 tiles, 3-stage cp.async, LDMATRIX
// fragment loads. FUSE=0: plain fp32 C. FUSE=1: fused norm+rope QKV.
// =====================================================================
#define SH 20
#define GSTG_W 5120
#define GEMM_SMEM_BYTES 61440

template<bool FUSE>
__global__ __launch_bounds__(256, 2)
void gemm_fp16_t(const uint32_t* __restrict__ A, const uint32_t* __restrict__ W,
                 float* __restrict__ C, const float* __restrict__ qg,
                 int K, int ldc, int coloff)
{
    extern __shared__ uint32_t sm[];
    const int KW   = K >> 1;
    const int tid  = threadIdx.x;
    const int lane = tid & 31;
    const int wid  = tid >> 5;
    const int wm   = wid & 3;
    const int wn   = wid >> 2;
    const int g    = lane >> 2;
    const int t    = lane & 3;
    const int m0   = blockIdx.y * 128;
    const int n0   = blockIdx.x * 128;
    const uint32_t smb = (uint32_t)__cvta_generic_to_shared(sm);

    const int rowA = lane & 15;
    const int aK   = (lane >> 4) << 2;
    uint32_t aoff[2];
    aoff[0] = (uint32_t)((wm * 32 + rowA) * SH + aK);
    aoff[1] = aoff[0] + 16 * SH;
    const int bn = (lane & 7) + ((lane & 16) >> 1);
    const int bK = ((lane >> 3) & 1) << 2;
    uint32_t boff[4];
#pragma unroll
    for (int p = 0; p < 4; p++)
        boff[p] = (uint32_t)(2560 + (wn * 64 + p * 16 + bn) * SH + bK);

    float acc[2][8][4];
#pragma unroll
    for (int mt = 0; mt < 2; mt++)
#pragma unroll
        for (int nt = 0; nt < 8; nt++)
#pragma unroll
            for (int c = 0; c < 4; c++) acc[mt][nt][c] = 0.f;

    const int ntile = K >> 5;

    auto load_tile = [&](int it, int s) {
        const uint32_t base = (uint32_t)s * GSTG_W;
        const size_t kwb = (size_t)it * 16;
#pragma unroll
        for (int r = 0; r < 2; r++) {
            int id = tid + 256 * r;
            int row = id >> 2, c4 = (id & 3) * 4;
            cpa16(smb + (base + row * SH + c4) * 4,
                  A + (size_t)(m0 + row) * KW + kwb + c4);
            cpa16(smb + (base + 2560 + row * SH + c4) * 4,
                  W + (size_t)(n0 + row) * KW + kwb + c4);
        }
        asm volatile("cp.async.commit_group;");
    };

    load_tile(0, 0);
    load_tile(1, 1);

    int s = 0;
    for (int it = 0; it < ntile; it++) {
        if (it + 1 < ntile) {
            asm volatile("cp.async.wait_group 1;");
        } else {
            asm volatile("cp.async.wait_group 0;");
        }
        __syncthreads();

        if (it + 2 < ntile) {
            int s2 = s + 2; if (s2 >= 3) s2 -= 3;
            load_tile(it + 2, s2);
        }

        const uint32_t sb4 = smb + (uint32_t)s * GSTG_W * 4;
#pragma unroll
        for (int h = 0; h < 2; h++) {
            const uint32_t kb4 = (uint32_t)(h * 8) * 4;
            uint32_t a[2][4];
            ldsm4(a[0], sb4 + aoff[0] * 4 + kb4);
            ldsm4(a[1], sb4 + aoff[1] * 4 + kb4);
#pragma unroll
            for (int p = 0; p < 4; p++) {
                uint32_t bq[4];
                ldsm4(bq, sb4 + boff[p] * 4 + kb4);
                mma_fp16(acc[0][p * 2    ], a[0], bq[0], bq[1]);
                mma_fp16(acc[1][p * 2    ], a[1], bq[0], bq[1]);
                mma_fp16(acc[0][p * 2 + 1], a[0], bq[2], bq[3]);
                mma_fp16(acc[1][p * 2 + 1], a[1], bq[2], bq[3]);
            }
        }
        if (++s >= 3) s = 0;
    }

    if (!FUSE) {
#pragma unroll
        for (int mt = 0; mt < 2; mt++) {
            int row = m0 + wm * 32 + mt * 16 + g;
#pragma unroll
            for (int nt = 0; nt < 8; nt++) {
                int col = coloff + n0 + wn * 64 + nt * 8 + 2 * t;
                float2 v01 = make_float2(acc[mt][nt][0], acc[mt][nt][1]);
                float2 v23 = make_float2(acc[mt][nt][2], acc[mt][nt][3]);
                *(float2*)(C + (size_t)row * ldc + col)       = v01;
                *(float2*)(C + (size_t)(row + 8) * ldc + col) = v23;
            }
        }
        return;
    }

    // ================= FUSED norm+rope epilogue (QKV) =================
    const int head  = n0 >> 7;
    const int bq    = m0 >> 11;
    const int sbase = m0 & (SS - 1);
    float* red = (float*)sm;

    float ss[2][2];
#pragma unroll
    for (int mt = 0; mt < 2; mt++) { ss[mt][0] = 0.f; ss[mt][1] = 0.f; }
#pragma unroll
    for (int mt = 0; mt < 2; mt++)
#pragma unroll
        for (int nt = 0; nt < 8; nt++) {
            ss[mt][0] += acc[mt][nt][0] * acc[mt][nt][0]
                       + acc[mt][nt][1] * acc[mt][nt][1];
            ss[mt][1] += acc[mt][nt][2] * acc[mt][nt][2]
                       + acc[mt][nt][3] * acc[mt][nt][3];
        }
#pragma unroll
    for (int mt = 0; mt < 2; mt++)
#pragma unroll
        for (int hf = 0; hf < 2; hf++) {
            ss[mt][hf] += __shfl_xor_sync(0xffffffffu, ss[mt][hf], 1);
            ss[mt][hf] += __shfl_xor_sync(0xffffffffu, ss[mt][hf], 2);
        }

    __syncthreads();
    if (t == 0) {
#pragma unroll
        for (int mt = 0; mt < 2; mt++) {
            red[wn * 128 + wm * 32 + mt * 16 + g]     = ss[mt][0];
            red[wn * 128 + wm * 32 + mt * 16 + g + 8] = ss[mt][1];
        }
    }
    __syncthreads();

    const float gscale = (head < 16) ? qg[head] * ATTN_SCALE : 1.0f;

#pragma unroll
    for (int mt = 0; mt < 2; mt++) {
#pragma unroll
        for (int hf = 0; hf < 2; hf++) {
            const int r  = wm * 32 + mt * 16 + g + hf * 8;
            const int sg = sbase + r;

            float vv[8][2];
            if (head < 20) {
                float sum = red[r] + red[128 + r];
                float rinv = rsqrtf(sum * (1.0f / HD) + 1.1920929e-07f) * gscale;
#pragma unroll
                for (int nt = 0; nt < 8; nt++) {
                    vv[nt][0] = acc[mt][nt][hf * 2 + 0] * rinv;
                    vv[nt][1] = acc[mt][nt][hf * 2 + 1] * rinv;
                }
                if (wn == 0) {
#pragma unroll
                    for (int nt = 0; nt < 4; nt++)
#pragma unroll
                        for (int j = 0; j < 2; j++) {
                            int f = nt * 8 + 2 * t + j;
                            float c  = g_cosr[sg * 32 + f];
                            float sn = g_sinr[sg * 32 + f];
                            float x1 = vv[nt][j], x2 = vv[nt + 4][j];
                            vv[nt][j]     =  x1 * c + x2 * sn;
                            vv[nt + 4][j] = -x1 * sn + x2 * c;
                        }
                }
                __half* dst = (head < 16)
                    ? g_qh + ((size_t)(bq * NH + head) * SS + sg) * HD
                    : g_kh + ((size_t)(bq * NKV + head - 16) * SS + sg) * HD;
                dst += wn * 64;
#pragma unroll
                for (int nt = 0; nt < 8; nt++)
                    *(uint32_t*)(dst + nt * 8 + 2 * t) = pack_h2(vv[nt][0], vv[nt][1]);
            } else {
                __half* dst = g_vh + (size_t)(bq * NKV + head - 20) * SS * HD
                            + (size_t)(sg & ~1) * HD + (sg & 1) + (size_t)wn * 128;
#pragma unroll
                for (int nt = 0; nt < 8; nt++) {
                    int c0 = nt * 8 + 2 * t;
                    dst[2 * c0]     = __float2half_rn(acc[mt][nt][hf * 2 + 0]);
                    dst[2 * c0 + 2] = __float2half_rn(acc[mt][nt][hf * 2 + 1]);
                }
            }
        }
    }
}

// =====================================================================
// fp16 flash attention; LDMATRIX for Q/K (S phase) and P (PV phase).
// Word strides: Q/K 68, P 36, V2 136 (scalar gather).
// =====================================================================
#define QS_OFF   0            // 128 x 68
#define KS_OFF   8704         // 64 x 68
#define VS_OFF0  13056        // 32 x 136
#define VS_OFF1  17408
#define PS_OFF   21760        // 128 x 36
#define PMAX_OFF 26368        // [2][128]
#define PSUM_OFF 26624        // [2][128]
#define MS_OFF   26880        // [128]
#define LS_OFF   27008        // [128]
#define ATTN_WORDS 27136      // 108,544 bytes

__global__ __launch_bounds__(256, 2)
void attn_mma(const __half* __restrict__ q, const __half* __restrict__ k,
              const __half* __restrict__ v, uint32_t* __restrict__ y)
{
    extern __shared__ uint32_t sm[];
    const int qb = (int)gridDim.x - 1 - (int)blockIdx.x;
    const int h = blockIdx.y, b = blockIdx.z;
    const int kvh = h >> 2;
    const int tid = threadIdx.x;
    const int lane = tid & 31, wid = tid >> 5;
    const int g = lane >> 2, t = lane & 3;
    const int wm = wid & 3, wn = wid >> 2;
    const int bar_id = 1 + wm;

    const __half* qbase = q + ((size_t)(b * NH + h) * SS + (size_t)qb * 128) * HD;
    const __half* kbase = k + ((size_t)(b * NKV + kvh) * SS) * HD;
    const __half* vbase = v + ((size_t)(b * NKV + kvh) * SS) * HD;  // paired

    const uint32_t smb = (uint32_t)__cvta_generic_to_shared(sm);

    // ldmatrix per-lane offsets
    const int rowA = lane & 15;
    const int aK   = (lane >> 4) << 2;
    const uint32_t qf0 = smb + (uint32_t)(QS_OFF + (wm * 32 + rowA) * 68 + aK) * 4;
    const uint32_t qf1 = qf0 + 16 * 68 * 4;
    const int bn = (lane & 7) + ((lane & 16) >> 1);
    const int bK = ((lane >> 3) & 1) << 2;
    const uint32_t kf0 = smb + (uint32_t)(KS_OFF + (wn * 32 + bn) * 68 + bK) * 4;
    const uint32_t kf1 = kf0 + 16 * 68 * 4;
    const uint32_t pf0 = smb + (uint32_t)(PS_OFF + (wm * 32 + rowA) * 36 + aK) * 4;
    const uint32_t pf1 = pf0 + 16 * 36 * 4;

    float* m_s  = (float*)(sm + MS_OFF);
    float* l_s  = (float*)(sm + LS_OFF);
    float* pmax = (float*)(sm + PMAX_OFF);
    float* psum = (float*)(sm + PSUM_OFF);

#pragma unroll
    for (int i = 0; i < 8; i++) {
        int id = tid + 256 * i;
        int row = id >> 4, c = id & 15;
        cpa16(smb + (QS_OFF + row * 68 + c * 4) * 4, qbase + (size_t)row * HD + c * 8);
    }
#pragma unroll
    for (int i = 0; i < 4; i++) {
        int id = tid + 256 * i;
        int row = id >> 4, c = id & 15;
        cpa16(smb + (KS_OFF + row * 68 + c * 4) * 4, kbase + (size_t)row * HD + c * 8);
    }
#pragma unroll
    for (int i = 0; i < 4; i++) {
        int id = tid + 256 * i;
        int row = id >> 5, c = id & 31;
        cpa16(smb + (VS_OFF0 + row * 136 + c * 4) * 4, vbase + (size_t)row * 256 + c * 8);
    }
    asm volatile("cp.async.commit_group;");

    if (tid < 128) { m_s[tid] = -1e30f; l_s[tid] = 0.f; }

    float oacc[2][8][4];
#pragma unroll
    for (int mt = 0; mt < 2; mt++)
#pragma unroll
        for (int nt = 0; nt < 8; nt++)
#pragma unroll
            for (int c = 0; c < 4; c++) oacc[mt][nt][c] = 0.f;

    const int nkv = 2 * qb + 2;

    asm volatile("cp.async.wait_group 0;");
    __syncthreads();

    for (int kvt = 0; kvt < nkv; kvt++) {
        const int cur = kvt & 1;

        // ---- S = Q K^T (ldmatrix fragments) ----
        float sacc[2][4][4];
#pragma unroll
        for (int mt = 0; mt < 2; mt++)
#pragma unroll
            for (int nt = 0; nt < 4; nt++)
#pragma unroll
                for (int c = 0; c < 4; c++) sacc[mt][nt][c] = 0.f;

#pragma unroll
        for (int ks = 0; ks < 8; ks++) {
            const uint32_t kb4 = (uint32_t)ks * 32;
            uint32_t a[2][4];
            ldsm4(a[0], qf0 + kb4);
            ldsm4(a[1], qf1 + kb4);
            uint32_t bq[4];
            ldsm4(bq, kf0 + kb4);
            mma_fp16(sacc[0][0], a[0], bq[0], bq[1]);
            mma_fp16(sacc[1][0], a[1], bq[0], bq[1]);
            mma_fp16(sacc[0][1], a[0], bq[2], bq[3]);
            mma_fp16(sacc[1][1], a[1], bq[2], bq[3]);
            ldsm4(bq, kf1 + kb4);
            mma_fp16(sacc[0][2], a[0], bq[0], bq[1]);
            mma_fp16(sacc[1][2], a[1], bq[0], bq[1]);
            mma_fp16(sacc[0][3], a[0], bq[2], bq[3]);
            mma_fp16(sacc[1][3], a[1], bq[2], bq[3]);
        }

        if (kvt >= 2 * qb) {
            const int off = (kvt - 2 * qb) * 64;
#pragma unroll
            for (int mt = 0; mt < 2; mt++) {
                int r0 = wm * 32 + mt * 16 + g, r1 = r0 + 8;
#pragma unroll
                for (int nt = 0; nt < 4; nt++) {
                    int c = wn * 32 + nt * 8 + 2 * t + off;
                    if (c     > r0) sacc[mt][nt][0] = -1e30f;
                    if (c + 1 > r0) sacc[mt][nt][1] = -1e30f;
                    if (c     > r1) sacc[mt][nt][2] = -1e30f;
                    if (c + 1 > r1) sacc[mt][nt][3] = -1e30f;
                }
            }
        }

#pragma unroll
        for (int mt = 0; mt < 2; mt++) {
            float rm0 = -1e30f, rm1 = -1e30f;
#pragma unroll
            for (int nt = 0; nt < 4; nt++) {
                rm0 = fmaxf(rm0, fmaxf(sacc[mt][nt][0], sacc[mt][nt][1]));
                rm1 = fmaxf(rm1, fmaxf(sacc[mt][nt][2], sacc[mt][nt][3]));
            }
            rm0 = fmaxf(rm0, __shfl_xor_sync(0xffffffffu, rm0, 1));
            rm0 = fmaxf(rm0, __shfl_xor_sync(0xffffffffu, rm0, 2));
            rm1 = fmaxf(rm1, __shfl_xor_sync(0xffffffffu, rm1, 1));
            rm1 = fmaxf(rm1, __shfl_xor_sync(0xffffffffu, rm1, 2));
            if (t == 0) {
                pmax[wn * 128 + wm * 32 + mt * 16 + g]     = rm0;
                pmax[wn * 128 + wm * 32 + mt * 16 + g + 8] = rm1;
            }
        }
        asm volatile("bar.sync %0, 64;" :: "r"(bar_id) : "memory");

        float alpha[2][2], mnew[2][2];
#pragma unroll
        for (int mt = 0; mt < 2; mt++) {
            int r0 = wm * 32 + mt * 16 + g, r1 = r0 + 8;
            float mo0 = m_s[r0], mo1 = m_s[r1];
            float mn0 = fmaxf(mo0, fmaxf(pmax[r0], pmax[128 + r0]));
            float mn1 = fmaxf(mo1, fmaxf(pmax[r1], pmax[128 + r1]));
            alpha[mt][0] = __expf(mo0 - mn0);
            alpha[mt][1] = __expf(mo1 - mn1);
            mnew[mt][0] = mn0; mnew[mt][1] = mn1;
            float rs0 = 0.f, rs1 = 0.f;
#pragma unroll
            for (int nt = 0; nt < 4; nt++) {
                float p00 = __expf(sacc[mt][nt][0] - mn0);
                float p01 = __expf(sacc[mt][nt][1] - mn0);
                float p10 = __expf(sacc[mt][nt][2] - mn1);
                float p11 = __expf(sacc[mt][nt][3] - mn1);
                rs0 += p00 + p01;
                rs1 += p10 + p11;
                int w = wn * 16 + nt * 4 + t;
                sm[PS_OFF + r0 * 36 + w] = pack_h2(p00, p01);
                sm[PS_OFF + r1 * 36 + w] = pack_h2(p10, p11);
            }
            rs0 += __shfl_xor_sync(0xffffffffu, rs0, 1);
            rs0 += __shfl_xor_sync(0xffffffffu, rs0, 2);
            rs1 += __shfl_xor_sync(0xffffffffu, rs1, 1);
            rs1 += __shfl_xor_sync(0xffffffffu, rs1, 2);
            if (t == 0) {
                psum[wn * 128 + r0] = rs0;
                psum[wn * 128 + r1] = rs1;
            }
        }
#pragma unroll
        for (int mt = 0; mt < 2; mt++)
#pragma unroll
            for (int nt = 0; nt < 8; nt++) {
                oacc[mt][nt][0] *= alpha[mt][0];
                oacc[mt][nt][1] *= alpha[mt][0];
                oacc[mt][nt][2] *= alpha[mt][1];
                oacc[mt][nt][3] *= alpha[mt][1];
            }
        asm volatile("bar.sync %0, 64;" :: "r"(bar_id) : "memory");
        if (wn == 0 && t == 0) {
#pragma unroll
            for (int mt = 0; mt < 2; mt++) {
                int r0 = wm * 32 + mt * 16 + g, r1 = r0 + 8;
                l_s[r0] = l_s[r0] * alpha[mt][0] + psum[r0] + psum[128 + r0];
                l_s[r1] = l_s[r1] * alpha[mt][1] + psum[r1] + psum[128 + r1];
                m_s[r0] = mnew[mt][0];
                m_s[r1] = mnew[mt][1];
            }
        }

        __syncthreads();
        if (kvt + 1 < nkv) {
            const __half* kn = kbase + (size_t)(kvt + 1) * 64 * HD;
            const __half* vn = vbase + (size_t)(kvt + 1) * 64 * HD;
            const uint32_t vo = cur ? VS_OFF0 : VS_OFF1;
#pragma unroll
            for (int i = 0; i < 4; i++) {
                int id = tid + 256 * i;
                int row = id >> 4, c = id & 15;
                cpa16(smb + (KS_OFF + row * 68 + c * 4) * 4, kn + (size_t)row * HD + c * 8);
            }
#pragma unroll
            for (int i = 0; i < 4; i++) {
                int id = tid + 256 * i;
                int row = id >> 5, c = id & 31;
                cpa16(smb + (vo + row * 136 + c * 4) * 4, vn + (size_t)row * 256 + c * 8);
            }
            asm volatile("cp.async.commit_group;");
        }

        // ---- O += P V (ldmatrix P fragments, scalar V gather) ----
        const uint32_t* Vb = sm + (cur ? VS_OFF1 : VS_OFF0) + wn * 64;
#pragma unroll
        for (int ks = 0; ks < 4; ks++) {
            const int kb = ks * 8;
            uint32_t a[2][4];
            ldsm4(a[0], pf0 + (uint32_t)kb * 4);
            ldsm4(a[1], pf1 + (uint32_t)kb * 4);
#pragma unroll
            for (int nt = 0; nt < 8; nt++) {
                uint32_t b0 = Vb[(kb + t) * 136 + nt * 8 + g];
                uint32_t b1 = Vb[(kb + t + 4) * 136 + nt * 8 + g];
                mma_fp16(oacc[0][nt], a[0], b0, b1);
                mma_fp16(oacc[1][nt], a[1], b0, b1);
            }
        }

        if (kvt + 1 < nkv) {
            asm volatile("cp.async.wait_group 0;");
            __syncthreads();
        }
    }

    asm volatile("bar.sync %0, 64;" :: "r"(bar_id) : "memory");

#pragma unroll
    for (int mt = 0; mt < 2; mt++) {
        int r0 = wm * 32 + mt * 16 + g, r1 = r0 + 8;
        float linv0 = 1.0f / l_s[r0];
        float linv1 = 1.0f / l_s[r1];
        uint32_t* y0 = y + ((size_t)b * SS + (size_t)qb * 128 + r0) * (DIM / 2)
                         + h * (HD / 2) + wn * 32;
        uint32_t* y1 = y + ((size_t)b * SS + (size_t)qb * 128 + r1) * (DIM / 2)
                         + h * (HD / 2) + wn * 32;
#pragma unroll
        for (int nt = 0; nt < 8; nt++) {
            y0[nt * 4 + t] = pack_h2(oacc[mt][nt][0] * linv0,
                                     oacc[mt][nt][1] * linv0);
            y1[nt * 4 + t] = pack_h2(oacc[mt][nt][2] * linv1,
                                     oacc[mt][nt][3] * linv1);
        }
    }
}

// =====================================================================
// host
// =====================================================================
extern "C" void kernel_launch(void* const* d_in, const int* in_sizes, int n_in,
                              void* d_out, int out_size)
{
    const float* x     = (const float*)d_in[0];
    const float* Wq    = (const float*)d_in[1];
    const float* Wk    = (const float*)d_in[2];
    const float* Wv    = (const float*)d_in[3];
    const float* Wproj = (const float*)d_in[4];
    const float* qg    = (const float*)d_in[5];
    float* out = (float*)d_out;

    __half *qh, *kh, *vh;
    uint32_t *y, *xt, *wt, *wpt;
    cudaGetSymbolAddress((void**)&qh,  g_qh);
    cudaGetSymbolAddress((void**)&kh,  g_kh);
    cudaGetSymbolAddress((void**)&vh,  g_vh);
    cudaGetSymbolAddress((void**)&y,   g_y);
    cudaGetSymbolAddress((void**)&xt,  g_xt);
    cudaGetSymbolAddress((void**)&wt,  g_wt);
    cudaGetSymbolAddress((void**)&wpt, g_wpt);

    cudaFuncSetAttribute(attn_mma,
                         cudaFuncAttributeMaxDynamicSharedMemorySize,
                         ATTN_WORDS * sizeof(uint32_t));
    cudaFuncSetAttribute(gemm_fp16_t<true>,
                         cudaFuncAttributeMaxDynamicSharedMemorySize,
                         GEMM_SMEM_BYTES);
    cudaFuncSetAttribute(gemm_fp16_t<false>,
                         cudaFuncAttributeMaxDynamicSharedMemorySize,
                         GEMM_SMEM_BYTES);

    // (0) RoPE tables
    rope_init<<<SS * 32 / 256, 256>>>();
    // (1) convert x -> fp16
    to_fp16<<<(MROWS * DIM / 4 + 255) / 256, 256>>>((const float4*)x, (uint2*)xt, MROWS * DIM / 4);
    // (2) convert Wq|Wk|Wv -> fp16
    to_fp16_w3<<<(QKVD * DIM / 4) / 256, 256>>>(
        (const float4*)Wq, (const float4*)Wk, (const float4*)Wv, (uint2*)wt);

    // (3) fused QKV projection + RMS-norm + RoPE -> q/k/v fp16  <-- ncu
    gemm_fp16_t<true><<<dim3(QKVD / 128, MROWS / 128), 256, GEMM_SMEM_BYTES>>>(
        xt, wt, nullptr, qg, DIM, 0, 0);

    // (4) fp16 flash attention -> g_y
    attn_mma<<<dim3(SS / 128, NH, BB), 256,
               ATTN_WORDS * sizeof(uint32_t)>>>(qh, kh, vh, y);

    // (5) convert Wproj -> fp16
    to_fp16<<<(DIM * DIM / 4 + 255) / 256, 256>>>((const float4*)Wproj, (uint2*)wpt, DIM * DIM / 4);

    // (6) output projection -> d_out
    gemm_fp16_t<false><<<dim3(DIM / 128, MROWS / 128), 256, GEMM_SMEM_BYTES>>>(
        y, wpt, out, qg, DIM, DIM, 0);
}

// round 17
// speedup vs baseline: 2.1113x; 1.0078x over previous
#include <cuda_runtime.h>
#include <cuda_fp16.h>
#include <math.h>
#include <stdint.h>

#define DIM 2048
#define NH 16
#define NKV 4
#define HD 128
#define BB 4
#define SS 2048
#define KVD 512        // NKV*HD
#define QKVD 3072      // DIM + 2*KVD
#define MROWS (BB*SS)  // 8192
#define ATTN_SCALE 0.08838834764831845f  // 1/sqrt(128)

// ---------------- scratch (no allocations allowed) ----------------
__device__ __half   g_qh[(size_t)BB*NH*SS*HD];     // fp16 q (scale folded)
__device__ __half   g_kh[(size_t)BB*NKV*SS*HD];    // fp16 k
__device__ __half   g_vh[(size_t)BB*NKV*HD*SS];    // fp16 v, D-MAJOR [b][kv][d][s]
__device__ uint32_t g_y[(size_t)BB*SS*DIM/2];      // fp16x2 (attn out)
__device__ uint32_t g_xt[(size_t)MROWS*DIM/2];     // fp16x2 of x
__device__ uint32_t g_wt[(size_t)QKVD*DIM/2];      // fp16x2 Wq|Wk|Wv
__device__ uint32_t g_wpt[(size_t)DIM*DIM/2];      // fp16x2 Wproj
__device__ float    g_cosr[SS*32];
__device__ float    g_sinr[SS*32];

// =====================================================================
// helpers
// =====================================================================
__device__ __forceinline__ void mma_fp16(float* c, const uint32_t* a,
                                         uint32_t b0, uint32_t b1) {
    asm volatile(
        "mma.sync.aligned.m16n8k16.row.col.f32.f16.f16.f32 "
        "{%0,%1,%2,%3}, {%4,%5,%6,%7}, {%8,%9}, {%0,%1,%2,%3};"
        : "+f"(c[0]), "+f"(c[1]), "+f"(c[2]), "+f"(c[3])
        : "r"(a[0]), "r"(a[1]), "r"(a[2]), "r"(a[3]), "r"(b0), "r"(b1));
}

__device__ __forceinline__ void ldsm4(uint32_t* r, uint32_t addr) {
    asm volatile("ldmatrix.sync.aligned.m8n8.x4.shared.b16 {%0,%1,%2,%3}, [%4];"
                 : "=r"(r[0]), "=r"(r[1]), "=r"(r[2]), "=r"(r[3]) : "r"(addr));
}

__device__ __forceinline__ void cpa16(uint32_t dst, const void* src) {
    asm volatile("cp.async.cg.shared.global [%0], [%1], 16;"
                 :: "r"(dst), "l"(src));
}

__device__ __forceinline__ uint32_t pack_h2(float x, float y) {
    __half2 h = __floats2half2_rn(x, y);
    return *(uint32_t*)&h;
}

// =====================================================================
// elementwise fp32 -> fp16x2 conversions
// =====================================================================
__global__ void to_fp16(const float4* __restrict__ src,
                        uint2* __restrict__ dst, int n4)
{
    int i = blockIdx.x * blockDim.x + threadIdx.x;
    if (i < n4) {
        float4 v = src[i];
        dst[i] = make_uint2(pack_h2(v.x, v.y), pack_h2(v.z, v.w));
    }
}

__global__ void to_fp16_w3(const float4* __restrict__ wq,
                           const float4* __restrict__ wk,
                           const float4* __restrict__ wv,
                           uint2* __restrict__ dst)
{
    int i = blockIdx.x * blockDim.x + threadIdx.x;
    const int nq = DIM * DIM / 4;
    const int nk = KVD * DIM / 4;
    float4 v;
    if (i < nq)            v = wq[i];
    else if (i < nq + nk)  v = wk[i - nq];
    else                   v = wv[i - nq - nk];
    dst[i] = make_uint2(pack_h2(v.x, v.y), pack_h2(v.z, v.w));
}

// =====================================================================
// RoPE table init
// =====================================================================
__global__ void rope_init()
{
    int i = blockIdx.x * blockDim.x + threadIdx.x;
    int s = i >> 5, f = i & 31;
    double inv = pow(10000.0, -(double)f / 32.0);
    double ang = (double)s * inv;
    double sd, cd;
    sincos(ang, &sd, &cd);
    g_cosr[i] = (float)cd;
    g_sinr[i] = (float)sd;
}

// =====================================================================
// fp16 warp-mma GEMM, 128x128x32 tiles, 4-stage cp.async pipeline with
// TWO k-tiles per barrier, LDMATRIX fragment loads.
// FUSE=0: plain fp32 C. FUSE=1: fused norm+rope QKV epilogue (V d-major).
// =====================================================================
#define SH 20
#define GSTG_W 5120
#define GEMM_SMEM_BYTES 81920      // 4 stages x 20,480 B

template<bool FUSE>
__global__ __launch_bounds__(256, 2)
void gemm_fp16_t(const uint32_t* __restrict__ A, const uint32_t* __restrict__ W,
                 float* __restrict__ C, const float* __restrict__ qg,
                 int K, int ldc, int coloff)
{
    extern __shared__ uint32_t sm[];
    const int KW   = K >> 1;
    const int tid  = threadIdx.x;
    const int lane = tid & 31;
    const int wid  = tid >> 5;
    const int wm   = wid & 3;
    const int wn   = wid >> 2;
    const int g    = lane >> 2;
    const int t    = lane & 3;
    const int m0   = blockIdx.y * 128;
    const int n0   = blockIdx.x * 128;
    const uint32_t smb = (uint32_t)__cvta_generic_to_shared(sm);

    const int rowA = lane & 15;
    const int aK   = (lane >> 4) << 2;
    uint32_t aoff[2];
    aoff[0] = (uint32_t)((wm * 32 + rowA) * SH + aK);
    aoff[1] = aoff[0] + 16 * SH;
    const int bn = (lane & 7) + ((lane & 16) >> 1);
    const int bK = ((lane >> 3) & 1) << 2;
    uint32_t boff[4];
#pragma unroll
    for (int p = 0; p < 4; p++)
        boff[p] = (uint32_t)(2560 + (wn * 64 + p * 16 + bn) * SH + bK);

    float acc[2][8][4];
#pragma unroll
    for (int mt = 0; mt < 2; mt++)
#pragma unroll
        for (int nt = 0; nt < 8; nt++)
#pragma unroll
            for (int c = 0; c < 4; c++) acc[mt][nt][c] = 0.f;

    const int ntile = K >> 5;          // even (64)

    auto load_tile = [&](int it, int s) {
        const uint32_t base = (uint32_t)s * GSTG_W;
        const size_t kwb = (size_t)it * 16;
#pragma unroll
        for (int r = 0; r < 2; r++) {
            int id = tid + 256 * r;
            int row = id >> 2, c4 = (id & 3) * 4;
            cpa16(smb + (base + row * SH + c4) * 4,
                  A + (size_t)(m0 + row) * KW + kwb + c4);
            cpa16(smb + (base + 2560 + row * SH + c4) * 4,
                  W + (size_t)(n0 + row) * KW + kwb + c4);
        }
        asm volatile("cp.async.commit_group;");
    };

    auto compute_stage = [&](int s) {
        const uint32_t sb4 = smb + (uint32_t)s * GSTG_W * 4;
#pragma unroll
        for (int h = 0; h < 2; h++) {
            const uint32_t kb4 = (uint32_t)(h * 8) * 4;
            uint32_t a[2][4];
            ldsm4(a[0], sb4 + aoff[0] * 4 + kb4);
            ldsm4(a[1], sb4 + aoff[1] * 4 + kb4);
#pragma unroll
            for (int p = 0; p < 4; p++) {
                uint32_t bq[4];
                ldsm4(bq, sb4 + boff[p] * 4 + kb4);
                mma_fp16(acc[0][p * 2    ], a[0], bq[0], bq[1]);
                mma_fp16(acc[1][p * 2    ], a[1], bq[0], bq[1]);
                mma_fp16(acc[0][p * 2 + 1], a[0], bq[2], bq[3]);
                mma_fp16(acc[1][p * 2 + 1], a[1], bq[2], bq[3]);
            }
        }
    };

    // prologue: tiles 0,1 -> stages 0,1
    load_tile(0, 0);
    load_tile(1, 1);

    for (int it = 0; it < ntile; it += 2) {
        asm volatile("cp.async.wait_group 0;");
        __syncthreads();
        if (it + 2 < ntile) {
            load_tile(it + 2, (it + 2) & 3);
            load_tile(it + 3, (it + 3) & 3);
        }
        compute_stage(it & 3);
        compute_stage((it + 1) & 3);
    }

    if (!FUSE) {
#pragma unroll
        for (int mt = 0; mt < 2; mt++) {
            int row = m0 + wm * 32 + mt * 16 + g;
#pragma unroll
            for (int nt = 0; nt < 8; nt++) {
                int col = coloff + n0 + wn * 64 + nt * 8 + 2 * t;
                float2 v01 = make_float2(acc[mt][nt][0], acc[mt][nt][1]);
                float2 v23 = make_float2(acc[mt][nt][2], acc[mt][nt][3]);
                *(float2*)(C + (size_t)row * ldc + col)       = v01;
                *(float2*)(C + (size_t)(row + 8) * ldc + col) = v23;
            }
        }
        return;
    }

    // ================= FUSED norm+rope epilogue (QKV) =================
    const int head  = n0 >> 7;
    const int bq    = m0 >> 11;
    const int sbase = m0 & (SS - 1);
    float* red = (float*)sm;

    float ss[2][2];
#pragma unroll
    for (int mt = 0; mt < 2; mt++) { ss[mt][0] = 0.f; ss[mt][1] = 0.f; }
#pragma unroll
    for (int mt = 0; mt < 2; mt++)
#pragma unroll
        for (int nt = 0; nt < 8; nt++) {
            ss[mt][0] += acc[mt][nt][0] * acc[mt][nt][0]
                       + acc[mt][nt][1] * acc[mt][nt][1];
            ss[mt][1] += acc[mt][nt][2] * acc[mt][nt][2]
                       + acc[mt][nt][3] * acc[mt][nt][3];
        }
#pragma unroll
    for (int mt = 0; mt < 2; mt++)
#pragma unroll
        for (int hf = 0; hf < 2; hf++) {
            ss[mt][hf] += __shfl_xor_sync(0xffffffffu, ss[mt][hf], 1);
            ss[mt][hf] += __shfl_xor_sync(0xffffffffu, ss[mt][hf], 2);
        }

    __syncthreads();
    if (t == 0) {
#pragma unroll
        for (int mt = 0; mt < 2; mt++) {
            red[wn * 128 + wm * 32 + mt * 16 + g]     = ss[mt][0];
            red[wn * 128 + wm * 32 + mt * 16 + g + 8] = ss[mt][1];
        }
    }
    __syncthreads();

    const float gscale = (head < 16) ? qg[head] * ATTN_SCALE : 1.0f;

#pragma unroll
    for (int mt = 0; mt < 2; mt++) {
#pragma unroll
        for (int hf = 0; hf < 2; hf++) {
            const int r  = wm * 32 + mt * 16 + g + hf * 8;
            const int sg = sbase + r;

            float vv[8][2];
            if (head < 20) {
                float sum = red[r] + red[128 + r];
                float rinv = rsqrtf(sum * (1.0f / HD) + 1.1920929e-07f) * gscale;
#pragma unroll
                for (int nt = 0; nt < 8; nt++) {
                    vv[nt][0] = acc[mt][nt][hf * 2 + 0] * rinv;
                    vv[nt][1] = acc[mt][nt][hf * 2 + 1] * rinv;
                }
                if (wn == 0) {
#pragma unroll
                    for (int nt = 0; nt < 4; nt++)
#pragma unroll
                        for (int j = 0; j < 2; j++) {
                            int f = nt * 8 + 2 * t + j;
                            float c  = g_cosr[sg * 32 + f];
                            float sn = g_sinr[sg * 32 + f];
                            float x1 = vv[nt][j], x2 = vv[nt + 4][j];
                            vv[nt][j]     =  x1 * c + x2 * sn;
                            vv[nt + 4][j] = -x1 * sn + x2 * c;
                        }
                }
                __half* dst = (head < 16)
                    ? g_qh + ((size_t)(bq * NH + head) * SS + sg) * HD
                    : g_kh + ((size_t)(bq * NKV + head - 16) * SS + sg) * HD;
                dst += wn * 64;
#pragma unroll
                for (int nt = 0; nt < 8; nt++)
                    *(uint32_t*)(dst + nt * 8 + 2 * t) = pack_h2(vv[nt][0], vv[nt][1]);
            } else {
                // V: d-major layout [b][kv][d][s]
                __half* dstv = g_vh
                    + ((size_t)(bq * NKV + head - 20) * HD + wn * 64) * SS + sg;
#pragma unroll
                for (int nt = 0; nt < 8; nt++) {
                    int d0 = nt * 8 + 2 * t;
                    dstv[(size_t)d0 * SS]       = __float2half_rn(acc[mt][nt][hf * 2 + 0]);
                    dstv[(size_t)(d0 + 1) * SS] = __float2half_rn(acc[mt][nt][hf * 2 + 1]);
                }
            }
        }
    }
}

// =====================================================================
// fp16 flash attention; LDMATRIX for Q/K (S), P and V (PV).
// Word strides: Q/K 68, P 36, VT 36. V tile in smem: [d=128][36].
// =====================================================================
#define QS_OFF   0            // 128 x 68
#define KS_OFF   8704         // 64 x 68
#define VT_OFF0  13056        // 128 x 36
#define VT_OFF1  17664
#define PS_OFF   22272        // 128 x 36
#define PMAX_OFF 26880        // [2][128]
#define PSUM_OFF 27136        // [2][128]
#define MS_OFF   27392        // [128]
#define LS_OFF   27520        // [128]
#define ATTN_WORDS 27648      // 110,592 bytes

__global__ __launch_bounds__(256, 2)
void attn_mma(const __half* __restrict__ q, const __half* __restrict__ k,
              const __half* __restrict__ v, uint32_t* __restrict__ y)
{
    extern __shared__ uint32_t sm[];
    const int qb = (int)gridDim.x - 1 - (int)blockIdx.x;
    const int h = blockIdx.y, b = blockIdx.z;
    const int kvh = h >> 2;
    const int tid = threadIdx.x;
    const int lane = tid & 31, wid = tid >> 5;
    const int g = lane >> 2, t = lane & 3;
    const int wm = wid & 3, wn = wid >> 2;
    const int bar_id = 1 + wm;

    const __half* qbase = q + ((size_t)(b * NH + h) * SS + (size_t)qb * 128) * HD;
    const __half* kbase = k + ((size_t)(b * NKV + kvh) * SS) * HD;
    const __half* vbase = v + (size_t)(b * NKV + kvh) * HD * SS;   // d-major

    const uint32_t smb = (uint32_t)__cvta_generic_to_shared(sm);

    // ldmatrix per-lane offsets
    const int rowA = lane & 15;
    const int aK   = (lane >> 4) << 2;
    const uint32_t qf0 = smb + (uint32_t)(QS_OFF + (wm * 32 + rowA) * 68 + aK) * 4;
    const uint32_t qf1 = qf0 + 16 * 68 * 4;
    const int bn = (lane & 7) + ((lane & 16) >> 1);
    const int bK = ((lane >> 3) & 1) << 2;
    const uint32_t kf0 = smb + (uint32_t)(KS_OFF + (wn * 32 + bn) * 68 + bK) * 4;
    const uint32_t kf1 = kf0 + 16 * 68 * 4;
    const uint32_t pf0 = smb + (uint32_t)(PS_OFF + (wm * 32 + rowA) * 36 + aK) * 4;
    const uint32_t pf1 = pf0 + 16 * 36 * 4;
    uint32_t vfoff[4];
#pragma unroll
    for (int p = 0; p < 4; p++)
        vfoff[p] = (uint32_t)((wn * 64 + p * 16 + bn) * 36 + bK) * 4;

    float* m_s  = (float*)(sm + MS_OFF);
    float* l_s  = (float*)(sm + LS_OFF);
    float* pmax = (float*)(sm + PMAX_OFF);
    float* psum = (float*)(sm + PSUM_OFF);

#pragma unroll
    for (int i = 0; i < 8; i++) {
        int id = tid + 256 * i;
        int row = id >> 4, c = id & 15;
        cpa16(smb + (QS_OFF + row * 68 + c * 4) * 4, qbase + (size_t)row * HD + c * 8);
    }
#pragma unroll
    for (int i = 0; i < 4; i++) {
        int id = tid + 256 * i;
        int row = id >> 4, c = id & 15;
        cpa16(smb + (KS_OFF + row * 68 + c * 4) * 4, kbase + (size_t)row * HD + c * 8);
    }
#pragma unroll
    for (int i = 0; i < 4; i++) {
        int id = tid + 256 * i;
        int row = id >> 3, c = id & 7;          // 128 rows x 8 chunks
        cpa16(smb + (VT_OFF0 + row * 36 + c * 4) * 4,
              vbase + (size_t)row * SS + c * 8);
    }
    asm volatile("cp.async.commit_group;");

    if (tid < 128) { m_s[tid] = -1e30f; l_s[tid] = 0.f; }

    float oacc[2][8][4];
#pragma unroll
    for (int mt = 0; mt < 2; mt++)
#pragma unroll
        for (int nt = 0; nt < 8; nt++)
#pragma unroll
            for (int c = 0; c < 4; c++) oacc[mt][nt][c] = 0.f;

    const int nkv = 2 * qb + 2;

    asm volatile("cp.async.wait_group 0;");
    __syncthreads();

    for (int kvt = 0; kvt < nkv; kvt++) {
        const int cur = kvt & 1;

        // ---- S = Q K^T (ldmatrix fragments) ----
        float sacc[2][4][4];
#pragma unroll
        for (int mt = 0; mt < 2; mt++)
#pragma unroll
            for (int nt = 0; nt < 4; nt++)
#pragma unroll
                for (int c = 0; c < 4; c++) sacc[mt][nt][c] = 0.f;

#pragma unroll
        for (int ks = 0; ks < 8; ks++) {
            const uint32_t kb4 = (uint32_t)ks * 32;
            uint32_t a[2][4];
            ldsm4(a[0], qf0 + kb4);
            ldsm4(a[1], qf1 + kb4);
            uint32_t bq[4];
            ldsm4(bq, kf0 + kb4);
            mma_fp16(sacc[0][0], a[0], bq[0], bq[1]);
            mma_fp16(sacc[1][0], a[1], bq[0], bq[1]);
            mma_fp16(sacc[0][1], a[0], bq[2], bq[3]);
            mma_fp16(sacc[1][1], a[1], bq[2], bq[3]);
            ldsm4(bq, kf1 + kb4);
            mma_fp16(sacc[0][2], a[0], bq[0], bq[1]);
            mma_fp16(sacc[1][2], a[1], bq[0], bq[1]);
            mma_fp16(sacc[0][3], a[0], bq[2], bq[3]);
            mma_fp16(sacc[1][3], a[1], bq[2], bq[3]);
        }

        if (kvt >= 2 * qb) {
            const int off = (kvt - 2 * qb) * 64;
#pragma unroll
            for (int mt = 0; mt < 2; mt++) {
                int r0 = wm * 32 + mt * 16 + g, r1 = r0 + 8;
#pragma unroll
                for (int nt = 0; nt < 4; nt++) {
                    int c = wn * 32 + nt * 8 + 2 * t + off;
                    if (c     > r0) sacc[mt][nt][0] = -1e30f;
                    if (c + 1 > r0) sacc[mt][nt][1] = -1e30f;
                    if (c     > r1) sacc[mt][nt][2] = -1e30f;
                    if (c + 1 > r1) sacc[mt][nt][3] = -1e30f;
                }
            }
        }

#pragma unroll
        for (int mt = 0; mt < 2; mt++) {
            float rm0 = -1e30f, rm1 = -1e30f;
#pragma unroll
            for (int nt = 0; nt < 4; nt++) {
                rm0 = fmaxf(rm0, fmaxf(sacc[mt][nt][0], sacc[mt][nt][1]));
                rm1 = fmaxf(rm1, fmaxf(sacc[mt][nt][2], sacc[mt][nt][3]));
            }
            rm0 = fmaxf(rm0, __shfl_xor_sync(0xffffffffu, rm0, 1));
            rm0 = fmaxf(rm0, __shfl_xor_sync(0xffffffffu, rm0, 2));
            rm1 = fmaxf(rm1, __shfl_xor_sync(0xffffffffu, rm1, 1));
            rm1 = fmaxf(rm1, __shfl_xor_sync(0xffffffffu, rm1, 2));
            if (t == 0) {
                pmax[wn * 128 + wm * 32 + mt * 16 + g]     = rm0;
                pmax[wn * 128 + wm * 32 + mt * 16 + g + 8] = rm1;
            }
        }
        asm volatile("bar.sync %0, 64;" :: "r"(bar_id) : "memory");

        float alpha[2][2], mnew[2][2];
#pragma unroll
        for (int mt = 0; mt < 2; mt++) {
            int r0 = wm * 32 + mt * 16 + g, r1 = r0 + 8;
            float mo0 = m_s[r0], mo1 = m_s[r1];
            float mn0 = fmaxf(mo0, fmaxf(pmax[r0], pmax[128 + r0]));
            float mn1 = fmaxf(mo1, fmaxf(pmax[r1], pmax[128 + r1]));
            alpha[mt][0] = __expf(mo0 - mn0);
            alpha[mt][1] = __expf(mo1 - mn1);
            mnew[mt][0] = mn0; mnew[mt][1] = mn1;
            float rs0 = 0.f, rs1 = 0.f;
#pragma unroll
            for (int nt = 0; nt < 4; nt++) {
                float p00 = __expf(sacc[mt][nt][0] - mn0);
                float p01 = __expf(sacc[mt][nt][1] - mn0);
                float p10 = __expf(sacc[mt][nt][2] - mn1);
                float p11 = __expf(sacc[mt][nt][3] - mn1);
                rs0 += p00 + p01;
                rs1 += p10 + p11;
                int w = wn * 16 + nt * 4 + t;
                sm[PS_OFF + r0 * 36 + w] = pack_h2(p00, p01);
                sm[PS_OFF + r1 * 36 + w] = pack_h2(p10, p11);
            }
            rs0 += __shfl_xor_sync(0xffffffffu, rs0, 1);
            rs0 += __shfl_xor_sync(0xffffffffu, rs0, 2);
            rs1 += __shfl_xor_sync(0xffffffffu, rs1, 1);
            rs1 += __shfl_xor_sync(0xffffffffu, rs1, 2);
            if (t == 0) {
                psum[wn * 128 + r0] = rs0;
                psum[wn * 128 + r1] = rs1;
            }
        }
#pragma unroll
        for (int mt = 0; mt < 2; mt++)
#pragma unroll
            for (int nt = 0; nt < 8; nt++) {
                oacc[mt][nt][0] *= alpha[mt][0];
                oacc[mt][nt][1] *= alpha[mt][0];
                oacc[mt][nt][2] *= alpha[mt][1];
                oacc[mt][nt][3] *= alpha[mt][1];
            }
        asm volatile("bar.sync %0, 64;" :: "r"(bar_id) : "memory");
        if (wn == 0 && t == 0) {
#pragma unroll
            for (int mt = 0; mt < 2; mt++) {
                int r0 = wm * 32 + mt * 16 + g, r1 = r0 + 8;
                l_s[r0] = l_s[r0] * alpha[mt][0] + psum[r0] + psum[128 + r0];
                l_s[r1] = l_s[r1] * alpha[mt][1] + psum[r1] + psum[128 + r1];
                m_s[r0] = mnew[mt][0];
                m_s[r1] = mnew[mt][1];
            }
        }

        __syncthreads();
        if (kvt + 1 < nkv) {
            const __half* kn = kbase + (size_t)(kvt + 1) * 64 * HD;
            const __half* vn = vbase + (size_t)(kvt + 1) * 64;   // s offset, d-major
            const uint32_t vo = cur ? VT_OFF0 : VT_OFF1;
#pragma unroll
            for (int i = 0; i < 4; i++) {
                int id = tid + 256 * i;
                int row = id >> 4, c = id & 15;
                cpa16(smb + (KS_OFF + row * 68 + c * 4) * 4, kn + (size_t)row * HD + c * 8);
            }
#pragma unroll
            for (int i = 0; i < 4; i++) {
                int id = tid + 256 * i;
                int row = id >> 3, c = id & 7;
                cpa16(smb + (vo + row * 36 + c * 4) * 4,
                      vn + (size_t)row * SS + c * 8);
            }
            asm volatile("cp.async.commit_group;");
        }

        // ---- O += P V (ldmatrix P and V fragments) ----
        const uint32_t vtb = smb + (uint32_t)(cur ? VT_OFF1 : VT_OFF0) * 4;
#pragma unroll
        for (int ks = 0; ks < 4; ks++) {
            const uint32_t kb4 = (uint32_t)ks * 32;
            uint32_t a[2][4];
            ldsm4(a[0], pf0 + kb4);
            ldsm4(a[1], pf1 + kb4);
#pragma unroll
            for (int p = 0; p < 4; p++) {
                uint32_t bq[4];
                ldsm4(bq, vtb + vfoff[p] + kb4);
                mma_fp16(oacc[0][p * 2    ], a[0], bq[0], bq[1]);
                mma_fp16(oacc[1][p * 2    ], a[1], bq[0], bq[1]);
                mma_fp16(oacc[0][p * 2 + 1], a[0], bq[2], bq[3]);
                mma_fp16(oacc[1][p * 2 + 1], a[1], bq[2], bq[3]);
            }
        }

        if (kvt + 1 < nkv) {
            asm volatile("cp.async.wait_group 0;");
            __syncthreads();
        }
    }

    asm volatile("bar.sync %0, 64;" :: "r"(bar_id) : "memory");

#pragma unroll
    for (int mt = 0; mt < 2; mt++) {
        int r0 = wm * 32 + mt * 16 + g, r1 = r0 + 8;
        float linv0 = 1.0f / l_s[r0];
        float linv1 = 1.0f / l_s[r1];
        uint32_t* y0 = y + ((size_t)b * SS + (size_t)qb * 128 + r0) * (DIM / 2)
                         + h * (HD / 2) + wn * 32;
        uint32_t* y1 = y + ((size_t)b * SS + (size_t)qb * 128 + r1) * (DIM / 2)
                         + h * (HD / 2) + wn * 32;
#pragma unroll
        for (int nt = 0; nt < 8; nt++) {
            y0[nt * 4 + t] = pack_h2(oacc[mt][nt][0] * linv0,
                                     oacc[mt][nt][1] * linv0);
            y1[nt * 4 + t] = pack_h2(oacc[mt][nt][2] * linv1,
                                     oacc[mt][nt][3] * linv1);
        }
    }
}

// =====================================================================
// host
// =====================================================================
extern "C" void kernel_launch(void* const* d_in, const int* in_sizes, int n_in,
                              void* d_out, int out_size)
{
    const float* x     = (const float*)d_in[0];
    const float* Wq    = (const float*)d_in[1];
    const float* Wk    = (const float*)d_in[2];
    const float* Wv    = (const float*)d_in[3];
    const float* Wproj = (const float*)d_in[4];
    const float* qg    = (const float*)d_in[5];
    float* out = (float*)d_out;

    __half *qh, *kh, *vh;
    uint32_t *y, *xt, *wt, *wpt;
    cudaGetSymbolAddress((void**)&qh,  g_qh);
    cudaGetSymbolAddress((void**)&kh,  g_kh);
    cudaGetSymbolAddress((void**)&vh,  g_vh);
    cudaGetSymbolAddress((void**)&y,   g_y);
    cudaGetSymbolAddress((void**)&xt,  g_xt);
    cudaGetSymbolAddress((void**)&wt,  g_wt);
    cudaGetSymbolAddress((void**)&wpt, g_wpt);

    cudaFuncSetAttribute(attn_mma,
                         cudaFuncAttributeMaxDynamicSharedMemorySize,
                         ATTN_WORDS * sizeof(uint32_t));
    cudaFuncSetAttribute(gemm_fp16_t<true>,
                         cudaFuncAttributeMaxDynamicSharedMemorySize,
                         GEMM_SMEM_BYTES);
    cudaFuncSetAttribute(gemm_fp16_t<false>,
                         cudaFuncAttributeMaxDynamicSharedMemorySize,
                         GEMM_SMEM_BYTES);

    // (0) RoPE tables
    rope_init<<<SS * 32 / 256, 256>>>();
    // (1) convert x -> fp16
    to_fp16<<<(MROWS * DIM / 4 + 255) / 256, 256>>>((const float4*)x, (uint2*)xt, MROWS * DIM / 4);
    // (2) convert Wq|Wk|Wv -> fp16
    to_fp16_w3<<<(QKVD * DIM / 4) / 256, 256>>>(
        (const float4*)Wq, (const float4*)Wk, (const float4*)Wv, (uint2*)wt);

    // (3) fused QKV projection + RMS-norm + RoPE -> q/k/v fp16  <-- ncu
    gemm_fp16_t<true><<<dim3(QKVD / 128, MROWS / 128), 256, GEMM_SMEM_BYTES>>>(
        xt, wt, nullptr, qg, DIM, 0, 0);

    // (4) fp16 flash attention -> g_y
    attn_mma<<<dim3(SS / 128, NH, BB), 256,
               ATTN_WORDS * sizeof(uint32_t)>>>(qh, kh, vh, y);

    // (5) convert Wproj -> fp16
    to_fp16<<<(DIM * DIM / 4 + 255) / 256, 256>>>((const float4*)Wproj, (uint2*)wpt, DIM * DIM / 4);

    // (6) output projection -> d_out
    gemm_fp16_t<false><<<dim3(DIM / 128, MROWS / 128), 256, GEMM_SMEM_BYTES>>>(
        y, wpt, out, qg, DIM, DIM, 0);
}